// round 3
// baseline (speedup 1.0000x reference)
#include <cuda_runtime.h>
#include <math.h>

// Problem constants (shapes fixed by the dataset)
#define NN 100000
#define FF 256
#define HH 128
#define CC 32
#define EMAX 1600000
#define NB_SCAN ((NN + 255) / 256)   // 391

// ---------------- scratch (device globals; no allocs allowed) ----------------
__device__ float g_h1[(size_t)NN * HH];     // X @ W1
__device__ float g_agg1[(size_t)NN * HH];   // aggregated layer-1
__device__ float g_h2[(size_t)NN * CC];     // relu(agg1+b1) @ W2
__device__ float g_dinv[NN];
__device__ int   g_counts[NN];
__device__ int   g_cursor[NN];
__device__ int   g_rowptr[NN];
__device__ int   g_csr_src[EMAX];
__device__ int   g_blksums[NB_SCAN];
__device__ int   g_blkoff[NB_SCAN];
__device__ int   g_is64;

// ---------------- edge-index dtype handling ----------------
// Reference code asks for int64, but default JAX demotes to int32.
// Detect on-device: if the high 32-bit word of the first 128 (assumed-int64)
// entries are all zero -> int64 layout; otherwise int32.
__global__ void detect_kernel(const unsigned* __restrict__ w) {
    __shared__ int nz;
    if (threadIdx.x == 0) nz = 0;
    __syncthreads();
    if (w[2 * threadIdx.x + 1] != 0u) atomicAdd(&nz, 1);
    __syncthreads();
    if (threadIdx.x == 0) g_is64 = (nz == 0) ? 1 : 0;
}

__device__ __forceinline__ int get_idx(const void* p, long long i) {
    if (g_is64) return (int)((const long long*)p)[i];
    return ((const int*)p)[i];
}

// ---------------- small kernels ----------------
__global__ void zero_kernel(int n) {
    int i = blockIdx.x * 256 + threadIdx.x;
    if (i < n) { g_counts[i] = 0; g_cursor[i] = 0; }
}

__global__ void hist_kernel(const void* __restrict__ idx, int E) {
    int i = blockIdx.x * 256 + threadIdx.x;
    if (i < E) {
        int d = get_idx(idx, (long long)E + i);
        atomicAdd(&g_counts[d], 1);
    }
}

__global__ void dinv_kernel(int n) {
    int i = blockIdx.x * 256 + threadIdx.x;
    if (i < n) {
        int c = g_counts[i];
        g_dinv[i] = (c > 0) ? rsqrtf((float)c) : 0.0f;
    }
}

// exclusive scan of g_counts into g_rowptr: 3 phases
__global__ void scan1_kernel(int n) {
    __shared__ int s[256];
    int t = threadIdx.x;
    int i = blockIdx.x * 256 + t;
    int v = (i < n) ? g_counts[i] : 0;
    s[t] = v;
    __syncthreads();
    for (int off = 1; off < 256; off <<= 1) {
        int x = (t >= off) ? s[t - off] : 0;
        __syncthreads();
        s[t] += x;
        __syncthreads();
    }
    if (i < n) g_rowptr[i] = s[t] - v;     // exclusive within block
    if (t == 255) g_blksums[blockIdx.x] = s[255];
}

__global__ void scan2_kernel(int nb) {
    __shared__ int s[512];
    int t = threadIdx.x;
    int v = (t < nb) ? g_blksums[t] : 0;
    s[t] = v;
    __syncthreads();
    for (int off = 1; off < 512; off <<= 1) {
        int x = (t >= off) ? s[t - off] : 0;
        __syncthreads();
        s[t] += x;
        __syncthreads();
    }
    if (t < nb) g_blkoff[t] = s[t] - v;    // exclusive
}

__global__ void scan3_kernel(int n) {
    int i = blockIdx.x * 256 + threadIdx.x;
    if (i < n) g_rowptr[i] += g_blkoff[i >> 8];
}

__global__ void scatter_kernel(const void* __restrict__ idx, int E) {
    int i = blockIdx.x * 256 + threadIdx.x;
    if (i < E) {
        int s = get_idx(idx, i);
        int d = get_idx(idx, (long long)E + i);
        int pos = g_rowptr[d] + atomicAdd(&g_cursor[d], 1);
        g_csr_src[pos] = s;
    }
}

// ---------------- GEMM1: h1 = X @ W1  (M x 256 x 128) ----------------
// Block: 256 threads, M-tile 64, full N=128, K chunked by 32.
__global__ __launch_bounds__(256) void gemm1_kernel(
    const float* __restrict__ X, const float* __restrict__ W, int M) {
    __shared__ float Xs[64 * 32];    // 8 KB
    __shared__ float Ws[32 * 128];   // 16 KB
    int t = threadIdx.x;
    int ty = t >> 5, tx = t & 31;
    int row0 = blockIdx.x * 64;

    float acc[8][4];
#pragma unroll
    for (int i = 0; i < 8; i++)
#pragma unroll
        for (int j = 0; j < 4; j++) acc[i][j] = 0.0f;

    for (int kk = 0; kk < FF; kk += 32) {
        // Xs: 64 rows x 32 cols = 512 float4
#pragma unroll
        for (int i = 0; i < 2; i++) {
            int idx = t + 256 * i;          // 0..511
            int r = idx >> 3, c4 = idx & 7; // r<64, c4<8
            float4 v = make_float4(0.f, 0.f, 0.f, 0.f);
            if (row0 + r < M)
                v = *(const float4*)&X[(size_t)(row0 + r) * FF + kk + c4 * 4];
            *(float4*)&Xs[r * 32 + c4 * 4] = v;
        }
        // Ws: 32 rows x 128 cols = 1024 float4
#pragma unroll
        for (int i = 0; i < 4; i++) {
            int idx = t + 256 * i;           // 0..1023
            int r = idx >> 5, c4 = idx & 31; // r<32, c4<32
            *(float4*)&Ws[r * 128 + c4 * 4] =
                *(const float4*)&W[(size_t)(kk + r) * HH + c4 * 4];
        }
        __syncthreads();
#pragma unroll 8
        for (int k = 0; k < 32; k++) {
            float b[4], a[8];
#pragma unroll
            for (int j = 0; j < 4; j++) b[j] = Ws[k * 128 + tx + 32 * j];
#pragma unroll
            for (int i = 0; i < 8; i++) a[i] = Xs[(ty + 8 * i) * 32 + k];
#pragma unroll
            for (int i = 0; i < 8; i++)
#pragma unroll
                for (int j = 0; j < 4; j++) acc[i][j] += a[i] * b[j];
        }
        __syncthreads();
    }
#pragma unroll
    for (int i = 0; i < 8; i++) {
        int row = row0 + ty + 8 * i;
        if (row < M) {
#pragma unroll
            for (int j = 0; j < 4; j++)
                g_h1[(size_t)row * HH + tx + 32 * j] = acc[i][j];
        }
    }
}

// ---------------- gather layer 1: agg1[n] = sum_src norm * h1[src] ----------------
// One warp per node; lane l owns float4 #l of the 128-wide feature row.
__global__ __launch_bounds__(256) void gather1_kernel(int n) {
    int node = (blockIdx.x << 3) + (threadIdx.x >> 5);
    int lane = threadIdx.x & 31;
    if (node >= n) return;
    float dn = g_dinv[node];
    int start = g_rowptr[node];
    int cnt = g_counts[node];
    float4 acc = make_float4(0.f, 0.f, 0.f, 0.f);
    const float4* h1v = (const float4*)g_h1;
    for (int j = 0; j < cnt; j++) {
        int s = g_csr_src[start + j];
        float w = g_dinv[s] * dn;
        float4 hv = h1v[(size_t)s * 32 + lane];
        acc.x += hv.x * w;
        acc.y += hv.y * w;
        acc.z += hv.z * w;
        acc.w += hv.w * w;
    }
    ((float4*)g_agg1)[(size_t)node * 32 + lane] = acc;
}

// ---------------- GEMM2 (fused relu(agg1+b1)): h2 = relu(agg1+b1) @ W2 ----------------
// Block: 256 threads, M-tile 32, full K=128, N=32.
__global__ __launch_bounds__(256) void gemm2_kernel(
    const float* __restrict__ b1, const float* __restrict__ W2, int M) {
    __shared__ float W2s[128 * 32];  // 16 KB
    __shared__ float As[32 * 128];   // 16 KB
    int t = threadIdx.x;
    int ty = t >> 5, tx = t & 31;
    int row0 = blockIdx.x * 32;

    // copy W2 (128x32 = 4096 floats)
#pragma unroll
    for (int i = 0; i < 16; i++) W2s[t + 256 * i] = W2[t + 256 * i];

    // load activation tile with fused bias + relu: 32x128 = 1024 float4
#pragma unroll
    for (int i = 0; i < 4; i++) {
        int idx = t + 256 * i;           // 0..1023
        int r = idx >> 5, c4 = idx & 31; // r<32, c4<32
        float4 v = make_float4(0.f, 0.f, 0.f, 0.f);
        if (row0 + r < M) {
            v = *(const float4*)&g_agg1[(size_t)(row0 + r) * HH + c4 * 4];
            v.x = fmaxf(v.x + b1[c4 * 4 + 0], 0.f);
            v.y = fmaxf(v.y + b1[c4 * 4 + 1], 0.f);
            v.z = fmaxf(v.z + b1[c4 * 4 + 2], 0.f);
            v.w = fmaxf(v.w + b1[c4 * 4 + 3], 0.f);
        }
        *(float4*)&As[r * 128 + c4 * 4] = v;
    }
    __syncthreads();

    float acc[4] = {0.f, 0.f, 0.f, 0.f};
#pragma unroll 8
    for (int k = 0; k < 128; k++) {
        float bv = W2s[k * 32 + tx];
#pragma unroll
        for (int i = 0; i < 4; i++) acc[i] += As[(ty + 8 * i) * 128 + k] * bv;
    }
#pragma unroll
    for (int i = 0; i < 4; i++) {
        int row = row0 + ty + 8 * i;
        if (row < M) g_h2[(size_t)row * CC + tx] = acc[i];
    }
}

// ---------------- gather layer 2 + bias + log_softmax (fused) ----------------
// One warp per node; lane = class index (C == 32).
__global__ __launch_bounds__(256) void final_kernel(
    const float* __restrict__ b2, float* __restrict__ out, int n) {
    int node = (blockIdx.x << 3) + (threadIdx.x >> 5);
    int lane = threadIdx.x & 31;
    if (node >= n) return;
    float dn = g_dinv[node];
    int start = g_rowptr[node];
    int cnt = g_counts[node];
    float acc = 0.f;
    for (int j = 0; j < cnt; j++) {
        int s = g_csr_src[start + j];
        float w = g_dinv[s] * dn;
        acc += g_h2[(size_t)s * CC + lane] * w;
    }
    float v = acc + b2[lane];
    // warp reductions over 32 classes
    float m = v;
#pragma unroll
    for (int o = 16; o > 0; o >>= 1) m = fmaxf(m, __shfl_xor_sync(0xffffffffu, m, o));
    float e = __expf(v - m);
    float ssum = e;
#pragma unroll
    for (int o = 16; o > 0; o >>= 1) ssum += __shfl_xor_sync(0xffffffffu, ssum, o);
    out[(size_t)node * CC + lane] = v - m - logf(ssum);
}

// ---------------- launcher ----------------
extern "C" void kernel_launch(void* const* d_in, const int* in_sizes, int n_in,
                              void* d_out, int out_size) {
    const float* X  = (const float*)d_in[0];
    const float* W1 = (const float*)d_in[1];
    const float* b1 = (const float*)d_in[2];
    const float* W2 = (const float*)d_in[3];
    const float* b2 = (const float*)d_in[4];
    const void*  EI = d_in[5];
    float* out = (float*)d_out;

    int N = in_sizes[0] / FF;   // 100000
    int E = in_sizes[5] / 2;    // 1600000 (element count is dtype-agnostic)

    int gN = (N + 255) / 256;
    int gE = (E + 255) / 256;
    int gW = (N + 7) / 8;       // warp-per-node kernels

    zero_kernel<<<gN, 256>>>(N);
    detect_kernel<<<1, 128>>>((const unsigned*)EI);
    hist_kernel<<<gE, 256>>>(EI, E);
    dinv_kernel<<<gN, 256>>>(N);
    scan1_kernel<<<gN, 256>>>(N);
    scan2_kernel<<<1, 512>>>(gN);
    scan3_kernel<<<gN, 256>>>(N);
    scatter_kernel<<<gE, 256>>>(EI, E);
    gemm1_kernel<<<(N + 63) / 64, 256>>>(X, W1, N);
    gather1_kernel<<<gW, 256>>>(N);
    gemm2_kernel<<<(N + 31) / 32, 256>>>(b1, W2, N);
    final_kernel<<<gW, 256>>>(b2, out, N);
}

// round 5
// speedup vs baseline: 1.2718x; 1.2718x over previous
#include <cuda_runtime.h>
#include <cuda_bf16.h>
#include <math.h>

// Problem constants (shapes fixed by the dataset)
#define NN 100000
#define FF 256
#define HH 128
#define CC 32
#define EMAX 1600000
#define NB_SCAN ((NN + 255) / 256)   // 391

// ---------------- scratch (device globals; no allocs allowed) ----------------
__device__ float g_h1[(size_t)NN * HH];     // X @ W1
__device__ float g_agg1[(size_t)NN * HH];   // aggregated layer-1
__device__ float g_h2[(size_t)NN * CC];     // relu(agg1+b1) @ W2
__device__ float g_dinv[NN];
__device__ int   g_counts[NN];
__device__ int   g_cursor[NN];
__device__ int   g_rowptr[NN];
__device__ int   g_csr_src[EMAX];
__device__ int   g_blksums[NB_SCAN];
__device__ int   g_blkoff[NB_SCAN];
__device__ int   g_is64;
__device__ __nv_bfloat16 g_W1hi[FF * HH];   // [N=128][K=256], K contiguous (col-major B)
__device__ __nv_bfloat16 g_W1lo[FF * HH];

// ---------------- edge-index dtype handling ----------------
// Reference asks for int64, default JAX demotes to int32. Detect on-device.
__global__ void detect_kernel(const unsigned* __restrict__ w) {
    __shared__ int nz;
    if (threadIdx.x == 0) nz = 0;
    __syncthreads();
    if (w[2 * threadIdx.x + 1] != 0u) atomicAdd(&nz, 1);
    __syncthreads();
    if (threadIdx.x == 0) g_is64 = (nz == 0) ? 1 : 0;
}

__device__ __forceinline__ int get_idx(const void* p, long long i) {
    if (g_is64) return (int)((const long long*)p)[i];
    return ((const int*)p)[i];
}

// ---------------- small kernels ----------------
__global__ void zero_kernel(int n) {
    int i = blockIdx.x * 256 + threadIdx.x;
    if (i < n) { g_counts[i] = 0; g_cursor[i] = 0; }
}

__global__ void hist_kernel(const void* __restrict__ idx, int E) {
    int i = blockIdx.x * 256 + threadIdx.x;
    if (i < E) {
        int d = get_idx(idx, (long long)E + i);
        atomicAdd(&g_counts[d], 1);
    }
}

__global__ void dinv_kernel(int n) {
    int i = blockIdx.x * 256 + threadIdx.x;
    if (i < n) {
        int c = g_counts[i];
        g_dinv[i] = (c > 0) ? rsqrtf((float)c) : 0.0f;
    }
}

__global__ void scan1_kernel(int n) {
    __shared__ int s[256];
    int t = threadIdx.x;
    int i = blockIdx.x * 256 + t;
    int v = (i < n) ? g_counts[i] : 0;
    s[t] = v;
    __syncthreads();
    for (int off = 1; off < 256; off <<= 1) {
        int x = (t >= off) ? s[t - off] : 0;
        __syncthreads();
        s[t] += x;
        __syncthreads();
    }
    if (i < n) g_rowptr[i] = s[t] - v;
    if (t == 255) g_blksums[blockIdx.x] = s[255];
}

__global__ void scan2_kernel(int nb) {
    __shared__ int s[512];
    int t = threadIdx.x;
    int v = (t < nb) ? g_blksums[t] : 0;
    s[t] = v;
    __syncthreads();
    for (int off = 1; off < 512; off <<= 1) {
        int x = (t >= off) ? s[t - off] : 0;
        __syncthreads();
        s[t] += x;
        __syncthreads();
    }
    if (t < nb) g_blkoff[t] = s[t] - v;
}

__global__ void scan3_kernel(int n) {
    int i = blockIdx.x * 256 + threadIdx.x;
    if (i < n) g_rowptr[i] += g_blkoff[i >> 8];
}

__global__ void scatter_kernel(const void* __restrict__ idx, int E) {
    int i = blockIdx.x * 256 + threadIdx.x;
    if (i < E) {
        int s = get_idx(idx, i);
        int d = get_idx(idx, (long long)E + i);
        int pos = g_rowptr[d] + atomicAdd(&g_cursor[d], 1);
        g_csr_src[pos] = s;
    }
}

// ---------------- W1 split: fp32 -> bf16 hi/lo, transposed to [N][K] ----------------
__global__ void prep_w1_kernel(const float* __restrict__ W1) {
    int i = blockIdx.x * 256 + threadIdx.x;
    if (i < FF * HH) {
        int n = i & (HH - 1);
        int k = i >> 7;
        float x = W1[(size_t)k * HH + n];
        __nv_bfloat16 h = __float2bfloat16_rn(x);
        g_W1hi[n * FF + k] = h;
        g_W1lo[n * FF + k] = __float2bfloat16_rn(x - __bfloat162float(h));
    }
}

// ---------------- GEMM1 via mma.sync bf16 split: h1 = X @ W1 ----------------
// Block 256 thr (8 warps), tile M=128 x N=128, K chunks of 32.
// Warp grid 4(m) x 2(n); warp tile 32(M) x 64(N); mma m16n8k16.
// 3 terms: Ah*Bh + Ah*Bl + Al*Bh (bf16 split of fp32, err ~2^-16).
#define SROW 40   // smem row stride in bf16 (80 bytes: 16B-aligned, conflict-free)

__device__ __forceinline__ unsigned pack_bf2(__nv_bfloat16 a, __nv_bfloat16 b) {
    __nv_bfloat162 t2;
    t2.x = a; t2.y = b;      // low half = a
    return *reinterpret_cast<unsigned*>(&t2);
}

__device__ __forceinline__ void mma16816(float* c, const unsigned* a, const unsigned* b) {
    asm volatile(
        "mma.sync.aligned.m16n8k16.row.col.f32.bf16.bf16.f32 "
        "{%0,%1,%2,%3}, {%4,%5,%6,%7}, {%8,%9}, {%0,%1,%2,%3};"
        : "+f"(c[0]), "+f"(c[1]), "+f"(c[2]), "+f"(c[3])
        : "r"(a[0]), "r"(a[1]), "r"(a[2]), "r"(a[3]),
          "r"(b[0]), "r"(b[1]));
}

__global__ void __launch_bounds__(256, 2) gemm1_mma_kernel(
    const float* __restrict__ X, int M) {
    __shared__ __align__(16) __nv_bfloat16 sAh[128 * SROW];
    __shared__ __align__(16) __nv_bfloat16 sAl[128 * SROW];
    __shared__ __align__(16) __nv_bfloat16 sBh[128 * SROW];
    __shared__ __align__(16) __nv_bfloat16 sBl[128 * SROW];

    int t = threadIdx.x;
    int lane = t & 31;
    int wid = t >> 5;
    int wm = wid & 3;          // 0..3 -> M offset wm*32
    int wn = wid >> 2;         // 0..1 -> N offset wn*64
    int g = lane >> 2;         // group id 0..7
    int tg = lane & 3;         // thread-in-group

    int row0 = blockIdx.x * 128;

    float acc[2][8][4];
#pragma unroll
    for (int mt = 0; mt < 2; mt++)
#pragma unroll
        for (int nt = 0; nt < 8; nt++)
#pragma unroll
            for (int j = 0; j < 4; j++) acc[mt][nt][j] = 0.0f;

    for (int chunk = 0; chunk < 8; chunk++) {
        int kk = chunk * 32;
        if (chunk) __syncthreads();   // previous compute done before overwrite

        // ---- A chunk: 128 rows x 32 k fp32 -> bf16 hi/lo (4096 elems, 16/thread) ----
#pragma unroll
        for (int i = 0; i < 4; i++) {
            int idx = t + 256 * i;          // 0..1023
            int r = idx >> 3;               // 0..127
            int c4 = idx & 7;               // float4 slot (4 floats each)
            float4 v = make_float4(0.f, 0.f, 0.f, 0.f);
            if (row0 + r < M)
                v = *(const float4*)&X[(size_t)(row0 + r) * FF + kk + c4 * 4];
            __nv_bfloat16 h0 = __float2bfloat16_rn(v.x);
            __nv_bfloat16 h1 = __float2bfloat16_rn(v.y);
            __nv_bfloat16 h2 = __float2bfloat16_rn(v.z);
            __nv_bfloat16 h3 = __float2bfloat16_rn(v.w);
            uint2 hi = make_uint2(pack_bf2(h0, h1), pack_bf2(h2, h3));
            uint2 lo = make_uint2(
                pack_bf2(__float2bfloat16_rn(v.x - __bfloat162float(h0)),
                         __float2bfloat16_rn(v.y - __bfloat162float(h1))),
                pack_bf2(__float2bfloat16_rn(v.z - __bfloat162float(h2)),
                         __float2bfloat16_rn(v.w - __bfloat162float(h3))));
            *(uint2*)&sAh[r * SROW + c4 * 4] = hi;
            *(uint2*)&sAl[r * SROW + c4 * 4] = lo;
        }
        // ---- B chunk: 128 n x 32 k bf16 copy (4096 elems, uint4 x2 per thread) ----
#pragma unroll
        for (int i = 0; i < 2; i++) {
            int id = t + 256 * i;           // 0..511
            int n = id >> 2;                // 0..127
            int kc = id & 3;                // 8-bf16 (16B) slot
            *(uint4*)&sBh[n * SROW + kc * 8] =
                *(const uint4*)&g_W1hi[n * FF + kk + kc * 8];
            *(uint4*)&sBl[n * SROW + kc * 8] =
                *(const uint4*)&g_W1lo[n * FF + kk + kc * 8];
        }
        __syncthreads();

        // ---- compute: 2 k16-steps ----
#pragma unroll
        for (int ks = 0; ks < 2; ks++) {
            int k0 = ks * 16;
            unsigned ah[2][4], al[2][4];
#pragma unroll
            for (int mt = 0; mt < 2; mt++) {
                int R = wm * 32 + mt * 16 + g;
                int base = R * SROW + k0 + tg * 2;
                ah[mt][0] = *(const unsigned*)&sAh[base];
                ah[mt][1] = *(const unsigned*)&sAh[base + 8 * SROW];
                ah[mt][2] = *(const unsigned*)&sAh[base + 8];
                ah[mt][3] = *(const unsigned*)&sAh[base + 8 * SROW + 8];
                al[mt][0] = *(const unsigned*)&sAl[base];
                al[mt][1] = *(const unsigned*)&sAl[base + 8 * SROW];
                al[mt][2] = *(const unsigned*)&sAl[base + 8];
                al[mt][3] = *(const unsigned*)&sAl[base + 8 * SROW + 8];
            }
#pragma unroll
            for (int nt = 0; nt < 8; nt++) {
                int Nb = wn * 64 + nt * 8 + g;
                int base = Nb * SROW + k0 + tg * 2;
                unsigned bh[2], bl[2];
                bh[0] = *(const unsigned*)&sBh[base];
                bh[1] = *(const unsigned*)&sBh[base + 8];
                bl[0] = *(const unsigned*)&sBl[base];
                bl[1] = *(const unsigned*)&sBl[base + 8];
#pragma unroll
                for (int mt = 0; mt < 2; mt++) {
                    mma16816(acc[mt][nt], ah[mt], bh);
                    mma16816(acc[mt][nt], ah[mt], bl);
                    mma16816(acc[mt][nt], al[mt], bh);
                }
            }
        }
    }

    // ---- epilogue: direct STG (float2 per fragment row) ----
#pragma unroll
    for (int mt = 0; mt < 2; mt++) {
        int r0 = row0 + wm * 32 + mt * 16 + g;
        int r1 = r0 + 8;
#pragma unroll
        for (int nt = 0; nt < 8; nt++) {
            int col = wn * 64 + nt * 8 + tg * 2;
            if (r0 < M)
                *(float2*)&g_h1[(size_t)r0 * HH + col] =
                    make_float2(acc[mt][nt][0], acc[mt][nt][1]);
            if (r1 < M)
                *(float2*)&g_h1[(size_t)r1 * HH + col] =
                    make_float2(acc[mt][nt][2], acc[mt][nt][3]);
        }
    }
}

// ---------------- gather layer 1: agg1[n] = sum_src norm * h1[src] ----------------
__global__ __launch_bounds__(256) void gather1_kernel(int n) {
    int node = (blockIdx.x << 3) + (threadIdx.x >> 5);
    int lane = threadIdx.x & 31;
    if (node >= n) return;
    float dn = g_dinv[node];
    int start = g_rowptr[node];
    int cnt = g_counts[node];
    float4 acc = make_float4(0.f, 0.f, 0.f, 0.f);
    const float4* h1v = (const float4*)g_h1;
    for (int j = 0; j < cnt; j++) {
        int s = g_csr_src[start + j];
        float w = g_dinv[s] * dn;
        float4 hv = h1v[(size_t)s * 32 + lane];
        acc.x += hv.x * w;
        acc.y += hv.y * w;
        acc.z += hv.z * w;
        acc.w += hv.w * w;
    }
    ((float4*)g_agg1)[(size_t)node * 32 + lane] = acc;
}

// ---------------- GEMM2 (fused relu(agg1+b1)): h2 = relu(agg1+b1) @ W2 ----------------
__global__ __launch_bounds__(256) void gemm2_kernel(
    const float* __restrict__ b1, const float* __restrict__ W2, int M) {
    __shared__ float W2s[128 * 32];
    __shared__ float As[32 * 128];
    int t = threadIdx.x;
    int ty = t >> 5, tx = t & 31;
    int row0 = blockIdx.x * 32;

#pragma unroll
    for (int i = 0; i < 16; i++) W2s[t + 256 * i] = W2[t + 256 * i];

#pragma unroll
    for (int i = 0; i < 4; i++) {
        int idx = t + 256 * i;
        int r = idx >> 5, c4 = idx & 31;
        float4 v = make_float4(0.f, 0.f, 0.f, 0.f);
        if (row0 + r < M) {
            v = *(const float4*)&g_agg1[(size_t)(row0 + r) * HH + c4 * 4];
            v.x = fmaxf(v.x + b1[c4 * 4 + 0], 0.f);
            v.y = fmaxf(v.y + b1[c4 * 4 + 1], 0.f);
            v.z = fmaxf(v.z + b1[c4 * 4 + 2], 0.f);
            v.w = fmaxf(v.w + b1[c4 * 4 + 3], 0.f);
        }
        *(float4*)&As[r * 128 + c4 * 4] = v;
    }
    __syncthreads();

    float acc[4] = {0.f, 0.f, 0.f, 0.f};
#pragma unroll 8
    for (int k = 0; k < 128; k++) {
        float bv = W2s[k * 32 + tx];
#pragma unroll
        for (int i = 0; i < 4; i++) acc[i] += As[(ty + 8 * i) * 128 + k] * bv;
    }
#pragma unroll
    for (int i = 0; i < 4; i++) {
        int row = row0 + ty + 8 * i;
        if (row < M) g_h2[(size_t)row * CC + tx] = acc[i];
    }
}

// ---------------- gather layer 2 + bias + log_softmax (fused) ----------------
__global__ __launch_bounds__(256) void final_kernel(
    const float* __restrict__ b2, float* __restrict__ out, int n) {
    int node = (blockIdx.x << 3) + (threadIdx.x >> 5);
    int lane = threadIdx.x & 31;
    if (node >= n) return;
    float dn = g_dinv[node];
    int start = g_rowptr[node];
    int cnt = g_counts[node];
    float acc = 0.f;
    for (int j = 0; j < cnt; j++) {
        int s = g_csr_src[start + j];
        float w = g_dinv[s] * dn;
        acc += g_h2[(size_t)s * CC + lane] * w;
    }
    float v = acc + b2[lane];
    float m = v;
#pragma unroll
    for (int o = 16; o > 0; o >>= 1) m = fmaxf(m, __shfl_xor_sync(0xffffffffu, m, o));
    float e = __expf(v - m);
    float ssum = e;
#pragma unroll
    for (int o = 16; o > 0; o >>= 1) ssum += __shfl_xor_sync(0xffffffffu, ssum, o);
    out[(size_t)node * CC + lane] = v - m - logf(ssum);
}

// ---------------- launcher ----------------
extern "C" void kernel_launch(void* const* d_in, const int* in_sizes, int n_in,
                              void* d_out, int out_size) {
    const float* X  = (const float*)d_in[0];
    const float* W1 = (const float*)d_in[1];
    const float* b1 = (const float*)d_in[2];
    const float* W2 = (const float*)d_in[3];
    const float* b2 = (const float*)d_in[4];
    const void*  EI = d_in[5];
    float* out = (float*)d_out;

    int N = in_sizes[0] / FF;   // 100000
    int E = in_sizes[5] / 2;    // 1600000

    int gN = (N + 255) / 256;
    int gE = (E + 255) / 256;
    int gW = (N + 7) / 8;

    zero_kernel<<<gN, 256>>>(N);
    detect_kernel<<<1, 128>>>((const unsigned*)EI);
    prep_w1_kernel<<<(FF * HH + 255) / 256, 256>>>(W1);
    hist_kernel<<<gE, 256>>>(EI, E);
    dinv_kernel<<<gN, 256>>>(N);
    scan1_kernel<<<gN, 256>>>(N);
    scan2_kernel<<<1, 512>>>(gN);
    scan3_kernel<<<gN, 256>>>(N);
    scatter_kernel<<<gE, 256>>>(EI, E);
    gemm1_mma_kernel<<<(N + 127) / 128, 256>>>(X, N);
    gather1_kernel<<<gW, 256>>>(N);
    gemm2_kernel<<<(N + 31) / 32, 256>>>(b1, W2, N);
    final_kernel<<<gW, 256>>>(b2, out, N);
}

// round 9
// speedup vs baseline: 1.2996x; 1.0219x over previous
#include <cuda_runtime.h>
#include <cuda_bf16.h>
#include <math.h>

// Problem constants (shapes fixed by the dataset)
#define NN 100000
#define FF 256
#define HH 128
#define CC 32
#define EMAX 1600000
#define NB_SCAN ((NN + 255) / 256)   // 391

// ---------------- scratch (device globals; no allocs allowed) ----------------
__device__ float g_h1[(size_t)NN * HH];     // X @ W1
__device__ float g_agg1[(size_t)NN * HH];   // aggregated layer-1
__device__ float g_h2[(size_t)NN * CC];     // relu(agg1+b1) @ W2
__device__ float g_dinv[NN];
__device__ int   g_counts[NN];
__device__ int   g_cursor[NN];
__device__ int   g_rowptr[NN];
__device__ int   g_csr_src[EMAX];
__device__ int   g_blksums[NB_SCAN];
__device__ int   g_blkoff[NB_SCAN];
__device__ int   g_is64;
__device__ __nv_bfloat16 g_W1hi[FF * HH];   // [N=128][K=256], K contiguous
__device__ __nv_bfloat16 g_W1lo[FF * HH];
__device__ __nv_bfloat16 g_W2hi[HH * CC];   // [N=32][K=128], K contiguous
__device__ __nv_bfloat16 g_W2lo[HH * CC];

__device__ __forceinline__ int get_idx(const void* p, long long i) {
    if (g_is64) return (int)((const long long*)p)[i];
    return ((const int*)p)[i];
}

// ---------------- fused zero + dtype detect ----------------
__global__ void zero_detect_kernel(const unsigned* __restrict__ w, int n) {
    int i = blockIdx.x * 256 + threadIdx.x;
    if (i < n) g_counts[i] = 0;
    if (blockIdx.x == 0 && threadIdx.x < 128) {
        __shared__ int nz;
        if (threadIdx.x == 0) nz = 0;
        __syncthreads();
        if (w[2 * threadIdx.x + 1] != 0u) atomicAdd(&nz, 1);
        __syncthreads();
        if (threadIdx.x == 0) g_is64 = (nz == 0) ? 1 : 0;
    }
}

// ---------------- W split: fp32 -> bf16 hi/lo, transposed to [N][K] ----------------
__global__ void prep_w_kernel(const float* __restrict__ W1, const float* __restrict__ W2) {
    int i = blockIdx.x * 256 + threadIdx.x;
    if (i < FF * HH) {
        int n = i & (HH - 1);
        int k = i >> 7;
        float x = W1[(size_t)k * HH + n];
        __nv_bfloat16 h = __float2bfloat16_rn(x);
        g_W1hi[n * FF + k] = h;
        g_W1lo[n * FF + k] = __float2bfloat16_rn(x - __bfloat162float(h));
    }
    if (i < HH * CC) {
        int n = i & (CC - 1);
        int k = i >> 5;
        float x = W2[(size_t)k * CC + n];
        __nv_bfloat16 h = __float2bfloat16_rn(x);
        g_W2hi[n * HH + k] = h;
        g_W2lo[n * HH + k] = __float2bfloat16_rn(x - __bfloat162float(h));
    }
}

// ---------------- hist: 4 edges per thread, vectorized loads ----------------
__global__ void hist_kernel(const void* __restrict__ idx, int E) {
    int base = (blockIdx.x * 256 + threadIdx.x) * 4;
    if (base >= E) return;
    if (base + 4 <= E) {
        int d0, d1, d2, d3;
        if (g_is64) {
            const longlong2* p = (const longlong2*)((const long long*)idx + E + base);
            longlong2 v0 = p[0], v1 = p[1];
            d0 = (int)v0.x; d1 = (int)v0.y; d2 = (int)v1.x; d3 = (int)v1.y;
        } else {
            int4 v = *(const int4*)((const int*)idx + E + base);
            d0 = v.x; d1 = v.y; d2 = v.z; d3 = v.w;
        }
        atomicAdd(&g_counts[d0], 1);
        atomicAdd(&g_counts[d1], 1);
        atomicAdd(&g_counts[d2], 1);
        atomicAdd(&g_counts[d3], 1);
    } else {
        for (int i = base; i < E; i++)
            atomicAdd(&g_counts[get_idx(idx, (long long)E + i)], 1);
    }
}

// ---------------- scans (dinv fused into scan1; cursor init in scan3) ----------------
__global__ void scan1_kernel(int n) {
    __shared__ int s[256];
    int t = threadIdx.x;
    int i = blockIdx.x * 256 + t;
    int v = (i < n) ? g_counts[i] : 0;
    if (i < n) g_dinv[i] = (v > 0) ? rsqrtf((float)v) : 0.0f;
    s[t] = v;
    __syncthreads();
    for (int off = 1; off < 256; off <<= 1) {
        int x = (t >= off) ? s[t - off] : 0;
        __syncthreads();
        s[t] += x;
        __syncthreads();
    }
    if (i < n) g_rowptr[i] = s[t] - v;
    if (t == 255) g_blksums[blockIdx.x] = s[255];
}

__global__ void scan2_kernel(int nb) {
    __shared__ int s[512];
    int t = threadIdx.x;
    int v = (t < nb) ? g_blksums[t] : 0;
    s[t] = v;
    __syncthreads();
    for (int off = 1; off < 512; off <<= 1) {
        int x = (t >= off) ? s[t - off] : 0;
        __syncthreads();
        s[t] += x;
        __syncthreads();
    }
    if (t < nb) g_blkoff[t] = s[t] - v;
}

__global__ void scan3_kernel(int n) {
    int i = blockIdx.x * 256 + threadIdx.x;
    if (i < n) {
        int r = g_rowptr[i] + g_blkoff[i >> 8];
        g_rowptr[i] = r;
        g_cursor[i] = r;          // scatter uses cursor directly as position
    }
}

// ---------------- scatter: 4 edges per thread ----------------
__global__ void scatter_kernel(const void* __restrict__ idx, int E) {
    int base = (blockIdx.x * 256 + threadIdx.x) * 4;
    if (base >= E) return;
    if (base + 4 <= E) {
        int s0, s1, s2, s3, d0, d1, d2, d3;
        if (g_is64) {
            const longlong2* ps = (const longlong2*)((const long long*)idx + base);
            const longlong2* pd = (const longlong2*)((const long long*)idx + E + base);
            longlong2 a0 = ps[0], a1 = ps[1], b0 = pd[0], b1 = pd[1];
            s0 = (int)a0.x; s1 = (int)a0.y; s2 = (int)a1.x; s3 = (int)a1.y;
            d0 = (int)b0.x; d1 = (int)b0.y; d2 = (int)b1.x; d3 = (int)b1.y;
        } else {
            int4 a = *(const int4*)((const int*)idx + base);
            int4 b = *(const int4*)((const int*)idx + E + base);
            s0 = a.x; s1 = a.y; s2 = a.z; s3 = a.w;
            d0 = b.x; d1 = b.y; d2 = b.z; d3 = b.w;
        }
        g_csr_src[atomicAdd(&g_cursor[d0], 1)] = s0;
        g_csr_src[atomicAdd(&g_cursor[d1], 1)] = s1;
        g_csr_src[atomicAdd(&g_cursor[d2], 1)] = s2;
        g_csr_src[atomicAdd(&g_cursor[d3], 1)] = s3;
    } else {
        for (int i = base; i < E; i++) {
            int s = get_idx(idx, i);
            int d = get_idx(idx, (long long)E + i);
            g_csr_src[atomicAdd(&g_cursor[d], 1)] = s;
        }
    }
}

// ---------------- mma helpers ----------------
#define SROW 40   // smem row stride in bf16 (80 bytes: 16B-aligned, conflict-free)

__device__ __forceinline__ unsigned pack_bf2(__nv_bfloat16 a, __nv_bfloat16 b) {
    __nv_bfloat162 t2;
    t2.x = a; t2.y = b;
    return *reinterpret_cast<unsigned*>(&t2);
}

__device__ __forceinline__ void mma16816(float* c, const unsigned* a, const unsigned* b) {
    asm volatile(
        "mma.sync.aligned.m16n8k16.row.col.f32.bf16.bf16.f32 "
        "{%0,%1,%2,%3}, {%4,%5,%6,%7}, {%8,%9}, {%0,%1,%2,%3};"
        : "+f"(c[0]), "+f"(c[1]), "+f"(c[2]), "+f"(c[3])
        : "r"(a[0]), "r"(a[1]), "r"(a[2]), "r"(a[3]),
          "r"(b[0]), "r"(b[1]));
}

// ---------------- GEMM1 via mma.sync bf16 split: h1 = X @ W1 ----------------
__global__ void __launch_bounds__(256, 2) gemm1_mma_kernel(
    const float* __restrict__ X, int M) {
    __shared__ __align__(16) __nv_bfloat16 sAh[128 * SROW];
    __shared__ __align__(16) __nv_bfloat16 sAl[128 * SROW];
    __shared__ __align__(16) __nv_bfloat16 sBh[128 * SROW];
    __shared__ __align__(16) __nv_bfloat16 sBl[128 * SROW];

    int t = threadIdx.x;
    int lane = t & 31;
    int wid = t >> 5;
    int wm = wid & 3;
    int wn = wid >> 2;
    int g = lane >> 2;
    int tg = lane & 3;
    int row0 = blockIdx.x * 128;

    float acc[2][8][4];
#pragma unroll
    for (int mt = 0; mt < 2; mt++)
#pragma unroll
        for (int nt = 0; nt < 8; nt++)
#pragma unroll
            for (int j = 0; j < 4; j++) acc[mt][nt][j] = 0.0f;

    for (int chunk = 0; chunk < 8; chunk++) {
        int kk = chunk * 32;
        if (chunk) __syncthreads();

#pragma unroll
        for (int i = 0; i < 4; i++) {
            int idx = t + 256 * i;
            int r = idx >> 3;
            int c4 = idx & 7;
            float4 v = make_float4(0.f, 0.f, 0.f, 0.f);
            if (row0 + r < M)
                v = *(const float4*)&X[(size_t)(row0 + r) * FF + kk + c4 * 4];
            __nv_bfloat16 h0 = __float2bfloat16_rn(v.x);
            __nv_bfloat16 h1 = __float2bfloat16_rn(v.y);
            __nv_bfloat16 h2 = __float2bfloat16_rn(v.z);
            __nv_bfloat16 h3 = __float2bfloat16_rn(v.w);
            uint2 hi = make_uint2(pack_bf2(h0, h1), pack_bf2(h2, h3));
            uint2 lo = make_uint2(
                pack_bf2(__float2bfloat16_rn(v.x - __bfloat162float(h0)),
                         __float2bfloat16_rn(v.y - __bfloat162float(h1))),
                pack_bf2(__float2bfloat16_rn(v.z - __bfloat162float(h2)),
                         __float2bfloat16_rn(v.w - __bfloat162float(h3))));
            *(uint2*)&sAh[r * SROW + c4 * 4] = hi;
            *(uint2*)&sAl[r * SROW + c4 * 4] = lo;
        }
#pragma unroll
        for (int i = 0; i < 2; i++) {
            int id = t + 256 * i;
            int n = id >> 2;
            int kc = id & 3;
            *(uint4*)&sBh[n * SROW + kc * 8] =
                *(const uint4*)&g_W1hi[n * FF + kk + kc * 8];
            *(uint4*)&sBl[n * SROW + kc * 8] =
                *(const uint4*)&g_W1lo[n * FF + kk + kc * 8];
        }
        __syncthreads();

#pragma unroll
        for (int ks = 0; ks < 2; ks++) {
            int k0 = ks * 16;
            unsigned ah[2][4], al[2][4];
#pragma unroll
            for (int mt = 0; mt < 2; mt++) {
                int R = wm * 32 + mt * 16 + g;
                int base = R * SROW + k0 + tg * 2;
                ah[mt][0] = *(const unsigned*)&sAh[base];
                ah[mt][1] = *(const unsigned*)&sAh[base + 8 * SROW];
                ah[mt][2] = *(const unsigned*)&sAh[base + 8];
                ah[mt][3] = *(const unsigned*)&sAh[base + 8 * SROW + 8];
                al[mt][0] = *(const unsigned*)&sAl[base];
                al[mt][1] = *(const unsigned*)&sAl[base + 8 * SROW];
                al[mt][2] = *(const unsigned*)&sAl[base + 8];
                al[mt][3] = *(const unsigned*)&sAl[base + 8 * SROW + 8];
            }
#pragma unroll
            for (int nt = 0; nt < 8; nt++) {
                int Nb = wn * 64 + nt * 8 + g;
                int base = Nb * SROW + k0 + tg * 2;
                unsigned bh[2], bl[2];
                bh[0] = *(const unsigned*)&sBh[base];
                bh[1] = *(const unsigned*)&sBh[base + 8];
                bl[0] = *(const unsigned*)&sBl[base];
                bl[1] = *(const unsigned*)&sBl[base + 8];
#pragma unroll
                for (int mt = 0; mt < 2; mt++) {
                    mma16816(acc[mt][nt], ah[mt], bh);
                    mma16816(acc[mt][nt], ah[mt], bl);
                    mma16816(acc[mt][nt], al[mt], bh);
                }
            }
        }
    }

#pragma unroll
    for (int mt = 0; mt < 2; mt++) {
        int r0 = row0 + wm * 32 + mt * 16 + g;
        int r1 = r0 + 8;
#pragma unroll
        for (int nt = 0; nt < 8; nt++) {
            int col = wn * 64 + nt * 8 + tg * 2;
            if (r0 < M)
                *(float2*)&g_h1[(size_t)r0 * HH + col] =
                    make_float2(acc[mt][nt][0], acc[mt][nt][1]);
            if (r1 < M)
                *(float2*)&g_h1[(size_t)r1 * HH + col] =
                    make_float2(acc[mt][nt][2], acc[mt][nt][3]);
        }
    }
}

// ---------------- gather layer 1 (lane-batched index fetch) ----------------
__global__ __launch_bounds__(256) void gather1_kernel(int n) {
    int node = (blockIdx.x << 3) + (threadIdx.x >> 5);
    int lane = threadIdx.x & 31;
    if (node >= n) return;
    float dn = g_dinv[node];
    int start = g_rowptr[node];
    int cnt = g_counts[node];
    float4 acc = make_float4(0.f, 0.f, 0.f, 0.f);
    const float4* h1v = (const float4*)g_h1;
    for (int j0 = 0; j0 < cnt; j0 += 32) {
        int nb = min(32, cnt - j0);
        int s = 0;
        float ds = 0.f;
        if (lane < nb) {
            s = g_csr_src[start + j0 + lane];
            ds = g_dinv[s];
        }
        for (int j = 0; j < nb; j++) {
            int sj = __shfl_sync(0xffffffffu, s, j);
            float w = __shfl_sync(0xffffffffu, ds, j) * dn;
            float4 hv = h1v[(size_t)sj * 32 + lane];
            acc.x += hv.x * w;
            acc.y += hv.y * w;
            acc.z += hv.z * w;
            acc.w += hv.w * w;
        }
    }
    ((float4*)g_agg1)[(size_t)node * 32 + lane] = acc;
}

// ---------------- GEMM2 via mma bf16 split: h2 = relu(agg1+b1) @ W2 ----------------
// Block 256 thr, tile M=128 x N=32, K=128 in 4 chunks of 32.
// Warp grid 4(m) x 2(n); warp tile 32(M) x 16(N).
__global__ void __launch_bounds__(256, 2) gemm2_mma_kernel(
    const float* __restrict__ b1, int M) {
    __shared__ __align__(16) __nv_bfloat16 sAh[128 * SROW];
    __shared__ __align__(16) __nv_bfloat16 sAl[128 * SROW];
    __shared__ __align__(16) __nv_bfloat16 sBh[32 * SROW];
    __shared__ __align__(16) __nv_bfloat16 sBl[32 * SROW];

    int t = threadIdx.x;
    int lane = t & 31;
    int wid = t >> 5;
    int wm = wid & 3;
    int wn = wid >> 2;
    int g = lane >> 2;
    int tg = lane & 3;
    int row0 = blockIdx.x * 128;

    float acc[2][2][4];
#pragma unroll
    for (int mt = 0; mt < 2; mt++)
#pragma unroll
        for (int nt = 0; nt < 2; nt++)
#pragma unroll
            for (int j = 0; j < 4; j++) acc[mt][nt][j] = 0.0f;

    for (int chunk = 0; chunk < 4; chunk++) {
        int kk = chunk * 32;
        if (chunk) __syncthreads();

        // A chunk: 128 rows x 32 k of relu(agg1+b1), split to bf16 hi/lo
#pragma unroll
        for (int i = 0; i < 4; i++) {
            int idx = t + 256 * i;
            int r = idx >> 3;
            int c4 = idx & 7;
            float4 v = make_float4(0.f, 0.f, 0.f, 0.f);
            if (row0 + r < M) {
                v = *(const float4*)&g_agg1[(size_t)(row0 + r) * HH + kk + c4 * 4];
                float4 b = *(const float4*)&b1[kk + c4 * 4];
                v.x = fmaxf(v.x + b.x, 0.f);
                v.y = fmaxf(v.y + b.y, 0.f);
                v.z = fmaxf(v.z + b.z, 0.f);
                v.w = fmaxf(v.w + b.w, 0.f);
            }
            __nv_bfloat16 h0 = __float2bfloat16_rn(v.x);
            __nv_bfloat16 h1 = __float2bfloat16_rn(v.y);
            __nv_bfloat16 h2 = __float2bfloat16_rn(v.z);
            __nv_bfloat16 h3 = __float2bfloat16_rn(v.w);
            uint2 hi = make_uint2(pack_bf2(h0, h1), pack_bf2(h2, h3));
            uint2 lo = make_uint2(
                pack_bf2(__float2bfloat16_rn(v.x - __bfloat162float(h0)),
                         __float2bfloat16_rn(v.y - __bfloat162float(h1))),
                pack_bf2(__float2bfloat16_rn(v.z - __bfloat162float(h2)),
                         __float2bfloat16_rn(v.w - __bfloat162float(h3))));
            *(uint2*)&sAh[r * SROW + c4 * 4] = hi;
            *(uint2*)&sAl[r * SROW + c4 * 4] = lo;
        }
        // B chunk: 32 n x 32 k bf16 copy (uint2 per thread)
        {
            int n = t >> 3;          // 0..31
            int kc = t & 7;          // 4-elem slot
            *(uint2*)&sBh[n * SROW + kc * 4] =
                *(const uint2*)&g_W2hi[n * HH + kk + kc * 4];
            *(uint2*)&sBl[n * SROW + kc * 4] =
                *(const uint2*)&g_W2lo[n * HH + kk + kc * 4];
        }
        __syncthreads();

#pragma unroll
        for (int ks = 0; ks < 2; ks++) {
            int k0 = ks * 16;
            unsigned ah[2][4], al[2][4];
#pragma unroll
            for (int mt = 0; mt < 2; mt++) {
                int R = wm * 32 + mt * 16 + g;
                int base = R * SROW + k0 + tg * 2;
                ah[mt][0] = *(const unsigned*)&sAh[base];
                ah[mt][1] = *(const unsigned*)&sAh[base + 8 * SROW];
                ah[mt][2] = *(const unsigned*)&sAh[base + 8];
                ah[mt][3] = *(const unsigned*)&sAh[base + 8 * SROW + 8];
                al[mt][0] = *(const unsigned*)&sAl[base];
                al[mt][1] = *(const unsigned*)&sAl[base + 8 * SROW];
                al[mt][2] = *(const unsigned*)&sAl[base + 8];
                al[mt][3] = *(const unsigned*)&sAl[base + 8 * SROW + 8];
            }
#pragma unroll
            for (int nt = 0; nt < 2; nt++) {
                int Nb = wn * 16 + nt * 8 + g;
                int base = Nb * SROW + k0 + tg * 2;
                unsigned bh[2], bl[2];
                bh[0] = *(const unsigned*)&sBh[base];
                bh[1] = *(const unsigned*)&sBh[base + 8];
                bl[0] = *(const unsigned*)&sBl[base];
                bl[1] = *(const unsigned*)&sBl[base + 8];
#pragma unroll
                for (int mt = 0; mt < 2; mt++) {
                    mma16816(acc[mt][nt], ah[mt], bh);
                    mma16816(acc[mt][nt], ah[mt], bl);
                    mma16816(acc[mt][nt], al[mt], bh);
                }
            }
        }
    }

#pragma unroll
    for (int mt = 0; mt < 2; mt++) {
        int r0 = row0 + wm * 32 + mt * 16 + g;
        int r1 = r0 + 8;
#pragma unroll
        for (int nt = 0; nt < 2; nt++) {
            int col = wn * 16 + nt * 8 + tg * 2;
            if (r0 < M)
                *(float2*)&g_h2[(size_t)r0 * CC + col] =
                    make_float2(acc[mt][nt][0], acc[mt][nt][1]);
            if (r1 < M)
                *(float2*)&g_h2[(size_t)r1 * CC + col] =
                    make_float2(acc[mt][nt][2], acc[mt][nt][3]);
        }
    }
}

// ---------------- gather layer 2 + bias + log_softmax (fused, batched) ----------------
__global__ __launch_bounds__(256) void final_kernel(
    const float* __restrict__ b2, float* __restrict__ out, int n) {
    int node = (blockIdx.x << 3) + (threadIdx.x >> 5);
    int lane = threadIdx.x & 31;
    if (node >= n) return;
    float dn = g_dinv[node];
    int start = g_rowptr[node];
    int cnt = g_counts[node];
    float acc = 0.f;
    for (int j0 = 0; j0 < cnt; j0 += 32) {
        int nb = min(32, cnt - j0);
        int s = 0;
        float ds = 0.f;
        if (lane < nb) {
            s = g_csr_src[start + j0 + lane];
            ds = g_dinv[s];
        }
        for (int j = 0; j < nb; j++) {
            int sj = __shfl_sync(0xffffffffu, s, j);
            float w = __shfl_sync(0xffffffffu, ds, j) * dn;
            acc += g_h2[(size_t)sj * CC + lane] * w;
        }
    }
    float v = acc + b2[lane];
    float m = v;
#pragma unroll
    for (int o = 16; o > 0; o >>= 1) m = fmaxf(m, __shfl_xor_sync(0xffffffffu, m, o));
    float e = __expf(v - m);
    float ssum = e;
#pragma unroll
    for (int o = 16; o > 0; o >>= 1) ssum += __shfl_xor_sync(0xffffffffu, ssum, o);
    out[(size_t)node * CC + lane] = v - m - logf(ssum);
}

// ---------------- launcher ----------------
extern "C" void kernel_launch(void* const* d_in, const int* in_sizes, int n_in,
                              void* d_out, int out_size) {
    const float* X  = (const float*)d_in[0];
    const float* W1 = (const float*)d_in[1];
    const float* b1 = (const float*)d_in[2];
    const float* W2 = (const float*)d_in[3];
    const float* b2 = (const float*)d_in[4];
    const void*  EI = d_in[5];
    float* out = (float*)d_out;

    int N = in_sizes[0] / FF;   // 100000
    int E = in_sizes[5] / 2;    // 1600000

    int gN = (N + 255) / 256;
    int gE4 = (E / 4 + 255) / 256;
    int gW = (N + 7) / 8;

    // launch order: gemm1 is #4 so the profiler (-s skip) captures it
    zero_detect_kernel<<<gN, 256>>>((const unsigned*)EI, N);     // 1
    prep_w_kernel<<<(FF * HH + 255) / 256, 256>>>(W1, W2);       // 2
    hist_kernel<<<gE4, 256>>>(EI, E);                            // 3
    gemm1_mma_kernel<<<(N + 127) / 128, 256>>>(X, N);            // 4
    scan1_kernel<<<gN, 256>>>(N);                                // 5
    scan2_kernel<<<1, 512>>>(gN);                                // 6
    scan3_kernel<<<gN, 256>>>(N);                                // 7
    scatter_kernel<<<gE4, 256>>>(EI, E);                         // 8
    gather1_kernel<<<gW, 256>>>(N);                              // 9
    gemm2_mma_kernel<<<(N + 127) / 128, 256>>>(b1, N);           // 10
    final_kernel<<<gW, 256>>>(b2, out, N);                       // 11
}

// round 11
// speedup vs baseline: 1.3488x; 1.0378x over previous
#include <cuda_runtime.h>
#include <cuda_bf16.h>
#include <math.h>

// Problem constants (shapes fixed by the dataset)
#define NN 100000
#define FF 256
#define HH 128
#define CC 32
#define EMAX 1600000
#define NB_SCAN ((NN + 255) / 256)   // 391

// ---------------- scratch (device globals; no allocs allowed) ----------------
__device__ float g_h1[(size_t)NN * HH];     // X @ W1
__device__ float g_agg1[(size_t)NN * HH];   // aggregated layer-1
__device__ float g_h2[(size_t)NN * CC];     // relu(agg1+b1) @ W2
__device__ float g_dinv[NN];
__device__ int   g_counts[NN];
__device__ int   g_cursor[NN];
__device__ int   g_rowptr[NN];
__device__ int   g_csr_src[EMAX];
__device__ int   g_blksums[NB_SCAN];
__device__ int   g_blkoff[NB_SCAN];
__device__ int   g_is64;
__device__ __nv_bfloat16 g_W1hi[FF * HH];   // [N=128][K=256], K contiguous
__device__ __nv_bfloat16 g_W1lo[FF * HH];
__device__ __nv_bfloat16 g_W2hi[HH * CC];   // [N=32][K=128], K contiguous
__device__ __nv_bfloat16 g_W2lo[HH * CC];

__device__ __forceinline__ int get_idx(const void* p, long long i) {
    if (g_is64) return (int)((const long long*)p)[i];
    return ((const int*)p)[i];
}

// ---------------- fused zero + dtype detect ----------------
__global__ void zero_detect_kernel(const unsigned* __restrict__ w, int n) {
    int i = blockIdx.x * 256 + threadIdx.x;
    if (i < n) g_counts[i] = 0;
    if (blockIdx.x == 0 && threadIdx.x < 128) {
        __shared__ int nz;
        if (threadIdx.x == 0) nz = 0;
        __syncthreads();
        if (w[2 * threadIdx.x + 1] != 0u) atomicAdd(&nz, 1);
        __syncthreads();
        if (threadIdx.x == 0) g_is64 = (nz == 0) ? 1 : 0;
    }
}

// ---------------- W split: fp32 -> bf16 hi/lo, transposed to [N][K] ----------------
__global__ void prep_w_kernel(const float* __restrict__ W1, const float* __restrict__ W2) {
    int i = blockIdx.x * 256 + threadIdx.x;
    if (i < FF * HH) {
        int n = i & (HH - 1);
        int k = i >> 7;
        float x = W1[(size_t)k * HH + n];
        __nv_bfloat16 h = __float2bfloat16_rn(x);
        g_W1hi[n * FF + k] = h;
        g_W1lo[n * FF + k] = __float2bfloat16_rn(x - __bfloat162float(h));
    }
    if (i < HH * CC) {
        int n = i & (CC - 1);
        int k = i >> 5;
        float x = W2[(size_t)k * CC + n];
        __nv_bfloat16 h = __float2bfloat16_rn(x);
        g_W2hi[n * HH + k] = h;
        g_W2lo[n * HH + k] = __float2bfloat16_rn(x - __bfloat162float(h));
    }
}

// ---------------- hist: 4 edges per thread, vectorized loads ----------------
__global__ void hist_kernel(const void* __restrict__ idx, int E) {
    int base = (blockIdx.x * 256 + threadIdx.x) * 4;
    if (base >= E) return;
    if (base + 4 <= E) {
        int d0, d1, d2, d3;
        if (g_is64) {
            const longlong2* p = (const longlong2*)((const long long*)idx + E + base);
            longlong2 v0 = p[0], v1 = p[1];
            d0 = (int)v0.x; d1 = (int)v0.y; d2 = (int)v1.x; d3 = (int)v1.y;
        } else {
            int4 v = *(const int4*)((const int*)idx + E + base);
            d0 = v.x; d1 = v.y; d2 = v.z; d3 = v.w;
        }
        atomicAdd(&g_counts[d0], 1);
        atomicAdd(&g_counts[d1], 1);
        atomicAdd(&g_counts[d2], 1);
        atomicAdd(&g_counts[d3], 1);
    } else {
        for (int i = base; i < E; i++)
            atomicAdd(&g_counts[get_idx(idx, (long long)E + i)], 1);
    }
}

// ---------------- scans (dinv fused into scan1; cursor init in scan3) ----------------
__global__ void scan1_kernel(int n) {
    __shared__ int s[256];
    int t = threadIdx.x;
    int i = blockIdx.x * 256 + t;
    int v = (i < n) ? g_counts[i] : 0;
    if (i < n) g_dinv[i] = (v > 0) ? rsqrtf((float)v) : 0.0f;
    s[t] = v;
    __syncthreads();
    for (int off = 1; off < 256; off <<= 1) {
        int x = (t >= off) ? s[t - off] : 0;
        __syncthreads();
        s[t] += x;
        __syncthreads();
    }
    if (i < n) g_rowptr[i] = s[t] - v;
    if (t == 255) g_blksums[blockIdx.x] = s[255];
}

__global__ void scan2_kernel(int nb) {
    __shared__ int s[512];
    int t = threadIdx.x;
    int v = (t < nb) ? g_blksums[t] : 0;
    s[t] = v;
    __syncthreads();
    for (int off = 1; off < 512; off <<= 1) {
        int x = (t >= off) ? s[t - off] : 0;
        __syncthreads();
        s[t] += x;
        __syncthreads();
    }
    if (t < nb) g_blkoff[t] = s[t] - v;
}

__global__ void scan3_kernel(int n) {
    int i = blockIdx.x * 256 + threadIdx.x;
    if (i < n) {
        int r = g_rowptr[i] + g_blkoff[i >> 8];
        g_rowptr[i] = r;
        g_cursor[i] = r;          // scatter uses cursor directly as position
    }
}

// ---------------- scatter: 4 edges per thread ----------------
__global__ void scatter_kernel(const void* __restrict__ idx, int E) {
    int base = (blockIdx.x * 256 + threadIdx.x) * 4;
    if (base >= E) return;
    if (base + 4 <= E) {
        int s0, s1, s2, s3, d0, d1, d2, d3;
        if (g_is64) {
            const longlong2* ps = (const longlong2*)((const long long*)idx + base);
            const longlong2* pd = (const longlong2*)((const long long*)idx + E + base);
            longlong2 a0 = ps[0], a1 = ps[1], b0 = pd[0], b1 = pd[1];
            s0 = (int)a0.x; s1 = (int)a0.y; s2 = (int)a1.x; s3 = (int)a1.y;
            d0 = (int)b0.x; d1 = (int)b0.y; d2 = (int)b1.x; d3 = (int)b1.y;
        } else {
            int4 a = *(const int4*)((const int*)idx + base);
            int4 b = *(const int4*)((const int*)idx + E + base);
            s0 = a.x; s1 = a.y; s2 = a.z; s3 = a.w;
            d0 = b.x; d1 = b.y; d2 = b.z; d3 = b.w;
        }
        g_csr_src[atomicAdd(&g_cursor[d0], 1)] = s0;
        g_csr_src[atomicAdd(&g_cursor[d1], 1)] = s1;
        g_csr_src[atomicAdd(&g_cursor[d2], 1)] = s2;
        g_csr_src[atomicAdd(&g_cursor[d3], 1)] = s3;
    } else {
        for (int i = base; i < E; i++) {
            int s = get_idx(idx, i);
            int d = get_idx(idx, (long long)E + i);
            g_csr_src[atomicAdd(&g_cursor[d], 1)] = s;
        }
    }
}

// ---------------- mma helpers ----------------
#define SROW 40   // smem row stride in bf16 (80 bytes: 16B-aligned; ldmatrix conflict-free)

__device__ __forceinline__ unsigned pack_bf2(__nv_bfloat16 a, __nv_bfloat16 b) {
    __nv_bfloat162 t2;
    t2.x = a; t2.y = b;
    return *reinterpret_cast<unsigned*>(&t2);
}

__device__ __forceinline__ void mma16816(float* c, const unsigned* a, const unsigned* b) {
    asm volatile(
        "mma.sync.aligned.m16n8k16.row.col.f32.bf16.bf16.f32 "
        "{%0,%1,%2,%3}, {%4,%5,%6,%7}, {%8,%9}, {%0,%1,%2,%3};"
        : "+f"(c[0]), "+f"(c[1]), "+f"(c[2]), "+f"(c[3])
        : "r"(a[0]), "r"(a[1]), "r"(a[2]), "r"(a[3]),
          "r"(b[0]), "r"(b[1]));
}

__device__ __forceinline__ void ldmx4(unsigned* r, const void* smem_ptr) {
    unsigned addr = (unsigned)__cvta_generic_to_shared(smem_ptr);
    asm volatile(
        "ldmatrix.sync.aligned.m8n8.x4.shared.b16 {%0,%1,%2,%3}, [%4];"
        : "=r"(r[0]), "=r"(r[1]), "=r"(r[2]), "=r"(r[3]) : "r"(addr));
}

// ---------------- GEMM1 via mma.sync bf16 split + ldmatrix: h1 = X @ W1 ----------------
__global__ void __launch_bounds__(256, 2) gemm1_mma_kernel(
    const float* __restrict__ X, int M) {
    __shared__ __align__(16) __nv_bfloat16 sAh[128 * SROW];
    __shared__ __align__(16) __nv_bfloat16 sAl[128 * SROW];
    __shared__ __align__(16) __nv_bfloat16 sBh[128 * SROW];
    __shared__ __align__(16) __nv_bfloat16 sBl[128 * SROW];

    int t = threadIdx.x;
    int lane = t & 31;
    int wid = t >> 5;
    int wm = wid & 3;
    int wn = wid >> 2;
    int g = lane >> 2;
    int tg = lane & 3;
    int row0 = blockIdx.x * 128;

    // ldmatrix per-lane tile coords
    int lrA = ((lane >> 3) & 1) * 8 + (lane & 7);  // row offset within m16
    int lcA = (lane >> 4) * 8;                     // k offset within k16
    int lrB = (lane >> 4) * 8 + (lane & 7);        // n offset within n16 pair
    int lcB = ((lane >> 3) & 1) * 8;               // k offset within k16

    float acc[2][8][4];
#pragma unroll
    for (int mt = 0; mt < 2; mt++)
#pragma unroll
        for (int nt = 0; nt < 8; nt++)
#pragma unroll
            for (int j = 0; j < 4; j++) acc[mt][nt][j] = 0.0f;

    for (int chunk = 0; chunk < 8; chunk++) {
        int kk = chunk * 32;
        if (chunk) __syncthreads();

#pragma unroll
        for (int i = 0; i < 4; i++) {
            int idx = t + 256 * i;
            int r = idx >> 3;
            int c4 = idx & 7;
            float4 v = make_float4(0.f, 0.f, 0.f, 0.f);
            if (row0 + r < M)
                v = *(const float4*)&X[(size_t)(row0 + r) * FF + kk + c4 * 4];
            __nv_bfloat16 h0 = __float2bfloat16_rn(v.x);
            __nv_bfloat16 h1 = __float2bfloat16_rn(v.y);
            __nv_bfloat16 h2 = __float2bfloat16_rn(v.z);
            __nv_bfloat16 h3 = __float2bfloat16_rn(v.w);
            uint2 hi = make_uint2(pack_bf2(h0, h1), pack_bf2(h2, h3));
            uint2 lo = make_uint2(
                pack_bf2(__float2bfloat16_rn(v.x - __bfloat162float(h0)),
                         __float2bfloat16_rn(v.y - __bfloat162float(h1))),
                pack_bf2(__float2bfloat16_rn(v.z - __bfloat162float(h2)),
                         __float2bfloat16_rn(v.w - __bfloat162float(h3))));
            *(uint2*)&sAh[r * SROW + c4 * 4] = hi;
            *(uint2*)&sAl[r * SROW + c4 * 4] = lo;
        }
#pragma unroll
        for (int i = 0; i < 2; i++) {
            int id = t + 256 * i;
            int n = id >> 2;
            int kc = id & 3;
            *(uint4*)&sBh[n * SROW + kc * 8] =
                *(const uint4*)&g_W1hi[n * FF + kk + kc * 8];
            *(uint4*)&sBl[n * SROW + kc * 8] =
                *(const uint4*)&g_W1lo[n * FF + kk + kc * 8];
        }
        __syncthreads();

#pragma unroll
        for (int ks = 0; ks < 2; ks++) {
            int k0 = ks * 16;
            unsigned ah[2][4], al[2][4];
#pragma unroll
            for (int mt = 0; mt < 2; mt++) {
                int R = (wm * 32 + mt * 16 + lrA) * SROW + k0 + lcA;
                ldmx4(ah[mt], &sAh[R]);
                ldmx4(al[mt], &sAl[R]);
            }
#pragma unroll
            for (int p = 0; p < 4; p++) {
                int Bo = (wn * 64 + p * 16 + lrB) * SROW + k0 + lcB;
                unsigned bh4[4], bl4[4];
                ldmx4(bh4, &sBh[Bo]);
                ldmx4(bl4, &sBl[Bo]);
#pragma unroll
                for (int mt = 0; mt < 2; mt++) {
                    mma16816(acc[mt][2 * p], ah[mt], bh4);
                    mma16816(acc[mt][2 * p], ah[mt], bl4);
                    mma16816(acc[mt][2 * p], al[mt], bh4);
                    mma16816(acc[mt][2 * p + 1], ah[mt], bh4 + 2);
                    mma16816(acc[mt][2 * p + 1], ah[mt], bl4 + 2);
                    mma16816(acc[mt][2 * p + 1], al[mt], bh4 + 2);
                }
            }
        }
    }

#pragma unroll
    for (int mt = 0; mt < 2; mt++) {
        int r0 = row0 + wm * 32 + mt * 16 + g;
        int r1 = r0 + 8;
#pragma unroll
        for (int nt = 0; nt < 8; nt++) {
            int col = wn * 64 + nt * 8 + tg * 2;
            if (r0 < M)
                *(float2*)&g_h1[(size_t)r0 * HH + col] =
                    make_float2(acc[mt][nt][0], acc[mt][nt][1]);
            if (r1 < M)
                *(float2*)&g_h1[(size_t)r1 * HH + col] =
                    make_float2(acc[mt][nt][2], acc[mt][nt][3]);
        }
    }
}

// ---------------- gather layer 1 (lane-batched index fetch) ----------------
__global__ __launch_bounds__(256) void gather1_kernel(int n) {
    int node = (blockIdx.x << 3) + (threadIdx.x >> 5);
    int lane = threadIdx.x & 31;
    if (node >= n) return;
    float dn = g_dinv[node];
    int start = g_rowptr[node];
    int cnt = g_counts[node];
    float4 acc = make_float4(0.f, 0.f, 0.f, 0.f);
    const float4* h1v = (const float4*)g_h1;
    for (int j0 = 0; j0 < cnt; j0 += 32) {
        int nb = min(32, cnt - j0);
        int s = 0;
        float ds = 0.f;
        if (lane < nb) {
            s = g_csr_src[start + j0 + lane];
            ds = g_dinv[s];
        }
        for (int j = 0; j < nb; j++) {
            int sj = __shfl_sync(0xffffffffu, s, j);
            float w = __shfl_sync(0xffffffffu, ds, j) * dn;
            float4 hv = h1v[(size_t)sj * 32 + lane];
            acc.x += hv.x * w;
            acc.y += hv.y * w;
            acc.z += hv.z * w;
            acc.w += hv.w * w;
        }
    }
    ((float4*)g_agg1)[(size_t)node * 32 + lane] = acc;
}

// ---------------- GEMM2 via mma bf16 split + ldmatrix: h2 = relu(agg1+b1) @ W2 ----------------
// Block 256 thr, tile M=128 x N=32, K=128 in 4 chunks of 32.
// Warp grid 4(m) x 2(n); warp tile 32(M) x 16(N).
__global__ void __launch_bounds__(256, 2) gemm2_mma_kernel(
    const float* __restrict__ b1, int M) {
    __shared__ __align__(16) __nv_bfloat16 sAh[128 * SROW];
    __shared__ __align__(16) __nv_bfloat16 sAl[128 * SROW];
    __shared__ __align__(16) __nv_bfloat16 sBh[32 * SROW];
    __shared__ __align__(16) __nv_bfloat16 sBl[32 * SROW];

    int t = threadIdx.x;
    int lane = t & 31;
    int wid = t >> 5;
    int wm = wid & 3;
    int wn = wid >> 2;
    int g = lane >> 2;
    int tg = lane & 3;
    int row0 = blockIdx.x * 128;

    int lrA = ((lane >> 3) & 1) * 8 + (lane & 7);
    int lcA = (lane >> 4) * 8;
    int lrB = (lane >> 4) * 8 + (lane & 7);
    int lcB = ((lane >> 3) & 1) * 8;

    float acc[2][2][4];
#pragma unroll
    for (int mt = 0; mt < 2; mt++)
#pragma unroll
        for (int nt = 0; nt < 2; nt++)
#pragma unroll
            for (int j = 0; j < 4; j++) acc[mt][nt][j] = 0.0f;

    for (int chunk = 0; chunk < 4; chunk++) {
        int kk = chunk * 32;
        if (chunk) __syncthreads();

        // A chunk: 128 rows x 32 k of relu(agg1+b1), split to bf16 hi/lo
#pragma unroll
        for (int i = 0; i < 4; i++) {
            int idx = t + 256 * i;
            int r = idx >> 3;
            int c4 = idx & 7;
            float4 v = make_float4(0.f, 0.f, 0.f, 0.f);
            if (row0 + r < M) {
                v = *(const float4*)&g_agg1[(size_t)(row0 + r) * HH + kk + c4 * 4];
                float4 b = *(const float4*)&b1[kk + c4 * 4];
                v.x = fmaxf(v.x + b.x, 0.f);
                v.y = fmaxf(v.y + b.y, 0.f);
                v.z = fmaxf(v.z + b.z, 0.f);
                v.w = fmaxf(v.w + b.w, 0.f);
            }
            __nv_bfloat16 h0 = __float2bfloat16_rn(v.x);
            __nv_bfloat16 h1 = __float2bfloat16_rn(v.y);
            __nv_bfloat16 h2 = __float2bfloat16_rn(v.z);
            __nv_bfloat16 h3 = __float2bfloat16_rn(v.w);
            uint2 hi = make_uint2(pack_bf2(h0, h1), pack_bf2(h2, h3));
            uint2 lo = make_uint2(
                pack_bf2(__float2bfloat16_rn(v.x - __bfloat162float(h0)),
                         __float2bfloat16_rn(v.y - __bfloat162float(h1))),
                pack_bf2(__float2bfloat16_rn(v.z - __bfloat162float(h2)),
                         __float2bfloat16_rn(v.w - __bfloat162float(h3))));
            *(uint2*)&sAh[r * SROW + c4 * 4] = hi;
            *(uint2*)&sAl[r * SROW + c4 * 4] = lo;
        }
        // B chunk: 32 n x 32 k bf16 copy (uint2 per thread)
        {
            int n = t >> 3;          // 0..31
            int kc = t & 7;          // 4-elem slot
            *(uint2*)&sBh[n * SROW + kc * 4] =
                *(const uint2*)&g_W2hi[n * HH + kk + kc * 4];
            *(uint2*)&sBl[n * SROW + kc * 4] =
                *(const uint2*)&g_W2lo[n * HH + kk + kc * 4];
        }
        __syncthreads();

#pragma unroll
        for (int ks = 0; ks < 2; ks++) {
            int k0 = ks * 16;
            unsigned ah[2][4], al[2][4];
#pragma unroll
            for (int mt = 0; mt < 2; mt++) {
                int R = (wm * 32 + mt * 16 + lrA) * SROW + k0 + lcA;
                ldmx4(ah[mt], &sAh[R]);
                ldmx4(al[mt], &sAl[R]);
            }
            {
                int Bo = (wn * 16 + lrB) * SROW + k0 + lcB;
                unsigned bh4[4], bl4[4];
                ldmx4(bh4, &sBh[Bo]);
                ldmx4(bl4, &sBl[Bo]);
#pragma unroll
                for (int mt = 0; mt < 2; mt++) {
                    mma16816(acc[mt][0], ah[mt], bh4);
                    mma16816(acc[mt][0], ah[mt], bl4);
                    mma16816(acc[mt][0], al[mt], bh4);
                    mma16816(acc[mt][1], ah[mt], bh4 + 2);
                    mma16816(acc[mt][1], ah[mt], bl4 + 2);
                    mma16816(acc[mt][1], al[mt], bh4 + 2);
                }
            }
        }
    }

#pragma unroll
    for (int mt = 0; mt < 2; mt++) {
        int r0 = row0 + wm * 32 + mt * 16 + g;
        int r1 = r0 + 8;
#pragma unroll
        for (int nt = 0; nt < 2; nt++) {
            int col = wn * 16 + nt * 8 + tg * 2;
            if (r0 < M)
                *(float2*)&g_h2[(size_t)r0 * CC + col] =
                    make_float2(acc[mt][nt][0], acc[mt][nt][1]);
            if (r1 < M)
                *(float2*)&g_h2[(size_t)r1 * CC + col] =
                    make_float2(acc[mt][nt][2], acc[mt][nt][3]);
        }
    }
}

// ---------------- gather layer 2 + bias + log_softmax (fused, batched) ----------------
__global__ __launch_bounds__(256) void final_kernel(
    const float* __restrict__ b2, float* __restrict__ out, int n) {
    int node = (blockIdx.x << 3) + (threadIdx.x >> 5);
    int lane = threadIdx.x & 31;
    if (node >= n) return;
    float dn = g_dinv[node];
    int start = g_rowptr[node];
    int cnt = g_counts[node];
    float acc = 0.f;
    for (int j0 = 0; j0 < cnt; j0 += 32) {
        int nb = min(32, cnt - j0);
        int s = 0;
        float ds = 0.f;
        if (lane < nb) {
            s = g_csr_src[start + j0 + lane];
            ds = g_dinv[s];
        }
        for (int j = 0; j < nb; j++) {
            int sj = __shfl_sync(0xffffffffu, s, j);
            float w = __shfl_sync(0xffffffffu, ds, j) * dn;
            acc += g_h2[(size_t)sj * CC + lane] * w;
        }
    }
    float v = acc + b2[lane];
    float m = v;
#pragma unroll
    for (int o = 16; o > 0; o >>= 1) m = fmaxf(m, __shfl_xor_sync(0xffffffffu, m, o));
    float e = __expf(v - m);
    float ssum = e;
#pragma unroll
    for (int o = 16; o > 0; o >>= 1) ssum += __shfl_xor_sync(0xffffffffu, ssum, o);
    out[(size_t)node * CC + lane] = v - m - logf(ssum);
}

// ---------------- launcher ----------------
extern "C" void kernel_launch(void* const* d_in, const int* in_sizes, int n_in,
                              void* d_out, int out_size) {
    const float* X  = (const float*)d_in[0];
    const float* W1 = (const float*)d_in[1];
    const float* b1 = (const float*)d_in[2];
    const float* W2 = (const float*)d_in[3];
    const float* b2 = (const float*)d_in[4];
    const void*  EI = d_in[5];
    float* out = (float*)d_out;

    int N = in_sizes[0] / FF;   // 100000
    int E = in_sizes[5] / 2;    // 1600000

    int gN = (N + 255) / 256;
    int gE4 = (E / 4 + 255) / 256;
    int gW = (N + 7) / 8;

    // launch order: gemm1 is #4 so the profiler (-s 5 -c 1) captures it
    zero_detect_kernel<<<gN, 256>>>((const unsigned*)EI, N);     // 1
    prep_w_kernel<<<(FF * HH + 255) / 256, 256>>>(W1, W2);       // 2
    hist_kernel<<<gE4, 256>>>(EI, E);                            // 3
    gemm1_mma_kernel<<<(N + 127) / 128, 256>>>(X, N);            // 4
    scan1_kernel<<<gN, 256>>>(N);                                // 5
    scan2_kernel<<<1, 512>>>(gN);                                // 6
    scan3_kernel<<<gN, 256>>>(N);                                // 7
    scatter_kernel<<<gE4, 256>>>(EI, E);                         // 8
    gather1_kernel<<<gW, 256>>>(N);                              // 9
    gemm2_mma_kernel<<<(N + 127) / 128, 256>>>(b1, N);           // 10
    final_kernel<<<gW, 256>>>(b2, out, N);                       // 11
}

// round 15
// speedup vs baseline: 1.4704x; 1.0902x over previous
#include <cuda_runtime.h>
#include <cuda_bf16.h>
#include <cuda_fp16.h>
#include <math.h>

// Problem constants (shapes fixed by the dataset)
#define NN 100000
#define FF 256
#define HH 128
#define CC 32
#define EMAX 1600000
#define NB_SCAN ((NN + 255) / 256)   // 391

// ---------------- scratch (device globals; no allocs allowed) ----------------
__device__ __half g_h1[(size_t)NN * HH];    // X @ W1 (fp16 to halve gather traffic)
__device__ float  g_agg1[(size_t)NN * HH];  // aggregated layer-1 (fp32)
__device__ __half g_h2[(size_t)NN * CC];    // relu(agg1+b1) @ W2 (fp16)
__device__ float g_dinv[NN];
__device__ int   g_counts[NN];
__device__ int   g_cursor[NN];
__device__ int   g_rowptr[NN];
__device__ int   g_csr_src[EMAX];
__device__ int   g_blksums[NB_SCAN];
__device__ int   g_blkoff[NB_SCAN];
__device__ int   g_is64;
__device__ __nv_bfloat16 g_W1hi[FF * HH];   // [N=128][K=256], K contiguous
__device__ __nv_bfloat16 g_W1lo[FF * HH];
__device__ __nv_bfloat16 g_W2hi[HH * CC];   // [N=32][K=128], K contiguous
__device__ __nv_bfloat16 g_W2lo[HH * CC];

__device__ __forceinline__ int get_idx(const void* p, long long i) {
    if (g_is64) return (int)((const long long*)p)[i];
    return ((const int*)p)[i];
}

// ---------------- fused zero + dtype detect ----------------
__global__ void zero_detect_kernel(const unsigned* __restrict__ w, int n) {
    int i = blockIdx.x * 256 + threadIdx.x;
    if (i < n) g_counts[i] = 0;
    if (blockIdx.x == 0 && threadIdx.x < 128) {
        __shared__ int nz;
        if (threadIdx.x == 0) nz = 0;
        __syncthreads();
        if (w[2 * threadIdx.x + 1] != 0u) atomicAdd(&nz, 1);
        __syncthreads();
        if (threadIdx.x == 0) g_is64 = (nz == 0) ? 1 : 0;
    }
}

// ---------------- W split: fp32 -> bf16 hi/lo, transposed to [N][K] ----------------
__global__ void prep_w_kernel(const float* __restrict__ W1, const float* __restrict__ W2) {
    int i = blockIdx.x * 256 + threadIdx.x;
    if (i < FF * HH) {
        int n = i & (HH - 1);
        int k = i >> 7;
        float x = W1[(size_t)k * HH + n];
        __nv_bfloat16 h = __float2bfloat16_rn(x);
        g_W1hi[n * FF + k] = h;
        g_W1lo[n * FF + k] = __float2bfloat16_rn(x - __bfloat162float(h));
    }
    if (i < HH * CC) {
        int n = i & (CC - 1);
        int k = i >> 5;
        float x = W2[(size_t)k * CC + n];
        __nv_bfloat16 h = __float2bfloat16_rn(x);
        g_W2hi[n * HH + k] = h;
        g_W2lo[n * HH + k] = __float2bfloat16_rn(x - __bfloat162float(h));
    }
}

// ---------------- hist: 4 edges per thread, vectorized loads ----------------
__global__ void hist_kernel(const void* __restrict__ idx, int E) {
    int base = (blockIdx.x * 256 + threadIdx.x) * 4;
    if (base >= E) return;
    if (base + 4 <= E) {
        int d0, d1, d2, d3;
        if (g_is64) {
            const longlong2* p = (const longlong2*)((const long long*)idx + E + base);
            longlong2 v0 = p[0], v1 = p[1];
            d0 = (int)v0.x; d1 = (int)v0.y; d2 = (int)v1.x; d3 = (int)v1.y;
        } else {
            int4 v = *(const int4*)((const int*)idx + E + base);
            d0 = v.x; d1 = v.y; d2 = v.z; d3 = v.w;
        }
        atomicAdd(&g_counts[d0], 1);
        atomicAdd(&g_counts[d1], 1);
        atomicAdd(&g_counts[d2], 1);
        atomicAdd(&g_counts[d3], 1);
    } else {
        for (int i = base; i < E; i++)
            atomicAdd(&g_counts[get_idx(idx, (long long)E + i)], 1);
    }
}

// ---------------- scans (dinv fused into scan1; cursor init in scan3) ----------------
__global__ void scan1_kernel(int n) {
    __shared__ int s[256];
    int t = threadIdx.x;
    int i = blockIdx.x * 256 + t;
    int v = (i < n) ? g_counts[i] : 0;
    if (i < n) g_dinv[i] = (v > 0) ? rsqrtf((float)v) : 0.0f;
    s[t] = v;
    __syncthreads();
    for (int off = 1; off < 256; off <<= 1) {
        int x = (t >= off) ? s[t - off] : 0;
        __syncthreads();
        s[t] += x;
        __syncthreads();
    }
    if (i < n) g_rowptr[i] = s[t] - v;
    if (t == 255) g_blksums[blockIdx.x] = s[255];
}

__global__ void scan2_kernel(int nb) {
    __shared__ int s[512];
    int t = threadIdx.x;
    int v = (t < nb) ? g_blksums[t] : 0;
    s[t] = v;
    __syncthreads();
    for (int off = 1; off < 512; off <<= 1) {
        int x = (t >= off) ? s[t - off] : 0;
        __syncthreads();
        s[t] += x;
        __syncthreads();
    }
    if (t < nb) g_blkoff[t] = s[t] - v;
}

__global__ void scan3_kernel(int n) {
    int i = blockIdx.x * 256 + threadIdx.x;
    if (i < n) {
        int r = g_rowptr[i] + g_blkoff[i >> 8];
        g_rowptr[i] = r;
        g_cursor[i] = r;          // scatter uses cursor directly as position
    }
}

// ---------------- scatter: 4 edges per thread ----------------
__global__ void scatter_kernel(const void* __restrict__ idx, int E) {
    int base = (blockIdx.x * 256 + threadIdx.x) * 4;
    if (base >= E) return;
    if (base + 4 <= E) {
        int s0, s1, s2, s3, d0, d1, d2, d3;
        if (g_is64) {
            const longlong2* ps = (const longlong2*)((const long long*)idx + base);
            const longlong2* pd = (const longlong2*)((const long long*)idx + E + base);
            longlong2 a0 = ps[0], a1 = ps[1], b0 = pd[0], b1 = pd[1];
            s0 = (int)a0.x; s1 = (int)a0.y; s2 = (int)a1.x; s3 = (int)a1.y;
            d0 = (int)b0.x; d1 = (int)b0.y; d2 = (int)b1.x; d3 = (int)b1.y;
        } else {
            int4 a = *(const int4*)((const int*)idx + base);
            int4 b = *(const int4*)((const int*)idx + E + base);
            s0 = a.x; s1 = a.y; s2 = a.z; s3 = a.w;
            d0 = b.x; d1 = b.y; d2 = b.z; d3 = b.w;
        }
        g_csr_src[atomicAdd(&g_cursor[d0], 1)] = s0;
        g_csr_src[atomicAdd(&g_cursor[d1], 1)] = s1;
        g_csr_src[atomicAdd(&g_cursor[d2], 1)] = s2;
        g_csr_src[atomicAdd(&g_cursor[d3], 1)] = s3;
    } else {
        for (int i = base; i < E; i++) {
            int s = get_idx(idx, i);
            int d = get_idx(idx, (long long)E + i);
            g_csr_src[atomicAdd(&g_cursor[d], 1)] = s;
        }
    }
}

// ---------------- mma helpers ----------------
#define SROW 40   // smem row stride in bf16 (80 bytes: 16B-aligned; ldmatrix conflict-free)

__device__ __forceinline__ unsigned pack_bf2(__nv_bfloat16 a, __nv_bfloat16 b) {
    __nv_bfloat162 t2;
    t2.x = a; t2.y = b;
    return *reinterpret_cast<unsigned*>(&t2);
}

__device__ __forceinline__ void mma16816(float* c, const unsigned* a, const unsigned* b) {
    asm volatile(
        "mma.sync.aligned.m16n8k16.row.col.f32.bf16.bf16.f32 "
        "{%0,%1,%2,%3}, {%4,%5,%6,%7}, {%8,%9}, {%0,%1,%2,%3};"
        : "+f"(c[0]), "+f"(c[1]), "+f"(c[2]), "+f"(c[3])
        : "r"(a[0]), "r"(a[1]), "r"(a[2]), "r"(a[3]),
          "r"(b[0]), "r"(b[1]));
}

__device__ __forceinline__ void ldmx4(unsigned* r, const void* smem_ptr) {
    unsigned addr = (unsigned)__cvta_generic_to_shared(smem_ptr);
    asm volatile(
        "ldmatrix.sync.aligned.m8n8.x4.shared.b16 {%0,%1,%2,%3}, [%4];"
        : "=r"(r[0]), "=r"(r[1]), "=r"(r[2]), "=r"(r[3]) : "r"(addr));
}

// ---------------- GEMM1 via mma.sync bf16 split + ldmatrix: h1 = X @ W1 ----------------
__global__ void __launch_bounds__(256, 2) gemm1_mma_kernel(
    const float* __restrict__ X, int M) {
    __shared__ __align__(16) __nv_bfloat16 sAh[128 * SROW];
    __shared__ __align__(16) __nv_bfloat16 sAl[128 * SROW];
    __shared__ __align__(16) __nv_bfloat16 sBh[128 * SROW];
    __shared__ __align__(16) __nv_bfloat16 sBl[128 * SROW];

    int t = threadIdx.x;
    int lane = t & 31;
    int wid = t >> 5;
    int wm = wid & 3;
    int wn = wid >> 2;
    int g = lane >> 2;
    int tg = lane & 3;
    int row0 = blockIdx.x * 128;

    // ldmatrix per-lane tile coords
    int lrA = ((lane >> 3) & 1) * 8 + (lane & 7);  // row offset within m16
    int lcA = (lane >> 4) * 8;                     // k offset within k16
    int lrB = (lane >> 4) * 8 + (lane & 7);        // n offset within n16 pair
    int lcB = ((lane >> 3) & 1) * 8;               // k offset within k16

    float acc[2][8][4];
#pragma unroll
    for (int mt = 0; mt < 2; mt++)
#pragma unroll
        for (int nt = 0; nt < 8; nt++)
#pragma unroll
            for (int j = 0; j < 4; j++) acc[mt][nt][j] = 0.0f;

    for (int chunk = 0; chunk < 8; chunk++) {
        int kk = chunk * 32;
        if (chunk) __syncthreads();

#pragma unroll
        for (int i = 0; i < 4; i++) {
            int idx = t + 256 * i;
            int r = idx >> 3;
            int c4 = idx & 7;
            float4 v = make_float4(0.f, 0.f, 0.f, 0.f);
            if (row0 + r < M)
                v = *(const float4*)&X[(size_t)(row0 + r) * FF + kk + c4 * 4];
            __nv_bfloat16 h0 = __float2bfloat16_rn(v.x);
            __nv_bfloat16 h1 = __float2bfloat16_rn(v.y);
            __nv_bfloat16 h2 = __float2bfloat16_rn(v.z);
            __nv_bfloat16 h3 = __float2bfloat16_rn(v.w);
            uint2 hi = make_uint2(pack_bf2(h0, h1), pack_bf2(h2, h3));
            uint2 lo = make_uint2(
                pack_bf2(__float2bfloat16_rn(v.x - __bfloat162float(h0)),
                         __float2bfloat16_rn(v.y - __bfloat162float(h1))),
                pack_bf2(__float2bfloat16_rn(v.z - __bfloat162float(h2)),
                         __float2bfloat16_rn(v.w - __bfloat162float(h3))));
            *(uint2*)&sAh[r * SROW + c4 * 4] = hi;
            *(uint2*)&sAl[r * SROW + c4 * 4] = lo;
        }
#pragma unroll
        for (int i = 0; i < 2; i++) {
            int id = t + 256 * i;
            int n = id >> 2;
            int kc = id & 3;
            *(uint4*)&sBh[n * SROW + kc * 8] =
                *(const uint4*)&g_W1hi[n * FF + kk + kc * 8];
            *(uint4*)&sBl[n * SROW + kc * 8] =
                *(const uint4*)&g_W1lo[n * FF + kk + kc * 8];
        }
        __syncthreads();

#pragma unroll
        for (int ks = 0; ks < 2; ks++) {
            int k0 = ks * 16;
            unsigned ah[2][4], al[2][4];
#pragma unroll
            for (int mt = 0; mt < 2; mt++) {
                int R = (wm * 32 + mt * 16 + lrA) * SROW + k0 + lcA;
                ldmx4(ah[mt], &sAh[R]);
                ldmx4(al[mt], &sAl[R]);
            }
#pragma unroll
            for (int p = 0; p < 4; p++) {
                int Bo = (wn * 64 + p * 16 + lrB) * SROW + k0 + lcB;
                unsigned bh4[4], bl4[4];
                ldmx4(bh4, &sBh[Bo]);
                ldmx4(bl4, &sBl[Bo]);
#pragma unroll
                for (int mt = 0; mt < 2; mt++) {
                    mma16816(acc[mt][2 * p], ah[mt], bh4);
                    mma16816(acc[mt][2 * p], ah[mt], bl4);
                    mma16816(acc[mt][2 * p], al[mt], bh4);
                    mma16816(acc[mt][2 * p + 1], ah[mt], bh4 + 2);
                    mma16816(acc[mt][2 * p + 1], ah[mt], bl4 + 2);
                    mma16816(acc[mt][2 * p + 1], al[mt], bh4 + 2);
                }
            }
        }
    }

    // epilogue: fp16 h1 (half2 stores)
#pragma unroll
    for (int mt = 0; mt < 2; mt++) {
        int r0 = row0 + wm * 32 + mt * 16 + g;
        int r1 = r0 + 8;
#pragma unroll
        for (int nt = 0; nt < 8; nt++) {
            int col = wn * 64 + nt * 8 + tg * 2;
            if (r0 < M)
                *(__half2*)&g_h1[(size_t)r0 * HH + col] =
                    __floats2half2_rn(acc[mt][nt][0], acc[mt][nt][1]);
            if (r1 < M)
                *(__half2*)&g_h1[(size_t)r1 * HH + col] =
                    __floats2half2_rn(acc[mt][nt][2], acc[mt][nt][3]);
        }
    }
}

// ---------------- gather layer 1 (fp16 h1, lane-batched index fetch) ----------------
// Lane owns 4 consecutive h1 columns (8 bytes) of the 128-wide row.
__global__ __launch_bounds__(256) void gather1_kernel(int n) {
    int node = (blockIdx.x << 3) + (threadIdx.x >> 5);
    int lane = threadIdx.x & 31;
    if (node >= n) return;
    float dn = g_dinv[node];
    int start = g_rowptr[node];
    int cnt = g_counts[node];
    float4 acc = make_float4(0.f, 0.f, 0.f, 0.f);
    const uint2* h1v = (const uint2*)g_h1;   // row = 32 uint2
    for (int j0 = 0; j0 < cnt; j0 += 32) {
        int nb = min(32, cnt - j0);
        int s = 0;
        float ds = 0.f;
        if (lane < nb) {
            s = g_csr_src[start + j0 + lane];
            ds = g_dinv[s];
        }
        for (int j = 0; j < nb; j++) {
            int sj = __shfl_sync(0xffffffffu, s, j);
            float w = __shfl_sync(0xffffffffu, ds, j) * dn;
            uint2 hv = h1v[(size_t)sj * 32 + lane];
            float2 f0 = __half22float2(*(__half2*)&hv.x);
            float2 f1 = __half22float2(*(__half2*)&hv.y);
            acc.x += f0.x * w;
            acc.y += f0.y * w;
            acc.z += f1.x * w;
            acc.w += f1.y * w;
        }
    }
    ((float4*)g_agg1)[(size_t)node * 32 + lane] = acc;
}

// ---------------- GEMM2 via mma bf16 split + ldmatrix: h2 = relu(agg1+b1) @ W2 ----------------
__global__ void __launch_bounds__(256, 2) gemm2_mma_kernel(
    const float* __restrict__ b1, int M) {
    __shared__ __align__(16) __nv_bfloat16 sAh[128 * SROW];
    __shared__ __align__(16) __nv_bfloat16 sAl[128 * SROW];
    __shared__ __align__(16) __nv_bfloat16 sBh[32 * SROW];
    __shared__ __align__(16) __nv_bfloat16 sBl[32 * SROW];

    int t = threadIdx.x;
    int lane = t & 31;
    int wid = t >> 5;
    int wm = wid & 3;
    int wn = wid >> 2;
    int g = lane >> 2;
    int tg = lane & 3;
    int row0 = blockIdx.x * 128;

    int lrA = ((lane >> 3) & 1) * 8 + (lane & 7);
    int lcA = (lane >> 4) * 8;
    int lrB = (lane >> 4) * 8 + (lane & 7);
    int lcB = ((lane >> 3) & 1) * 8;

    float acc[2][2][4];
#pragma unroll
    for (int mt = 0; mt < 2; mt++)
#pragma unroll
        for (int nt = 0; nt < 2; nt++)
#pragma unroll
            for (int j = 0; j < 4; j++) acc[mt][nt][j] = 0.0f;

    for (int chunk = 0; chunk < 4; chunk++) {
        int kk = chunk * 32;
        if (chunk) __syncthreads();

        // A chunk: 128 rows x 32 k of relu(agg1+b1), split to bf16 hi/lo
#pragma unroll
        for (int i = 0; i < 4; i++) {
            int idx = t + 256 * i;
            int r = idx >> 3;
            int c4 = idx & 7;
            float4 v = make_float4(0.f, 0.f, 0.f, 0.f);
            if (row0 + r < M) {
                v = *(const float4*)&g_agg1[(size_t)(row0 + r) * HH + kk + c4 * 4];
                float4 b = *(const float4*)&b1[kk + c4 * 4];
                v.x = fmaxf(v.x + b.x, 0.f);
                v.y = fmaxf(v.y + b.y, 0.f);
                v.z = fmaxf(v.z + b.z, 0.f);
                v.w = fmaxf(v.w + b.w, 0.f);
            }
            __nv_bfloat16 h0 = __float2bfloat16_rn(v.x);
            __nv_bfloat16 h1 = __float2bfloat16_rn(v.y);
            __nv_bfloat16 h2 = __float2bfloat16_rn(v.z);
            __nv_bfloat16 h3 = __float2bfloat16_rn(v.w);
            uint2 hi = make_uint2(pack_bf2(h0, h1), pack_bf2(h2, h3));
            uint2 lo = make_uint2(
                pack_bf2(__float2bfloat16_rn(v.x - __bfloat162float(h0)),
                         __float2bfloat16_rn(v.y - __bfloat162float(h1))),
                pack_bf2(__float2bfloat16_rn(v.z - __bfloat162float(h2)),
                         __float2bfloat16_rn(v.w - __bfloat162float(h3))));
            *(uint2*)&sAh[r * SROW + c4 * 4] = hi;
            *(uint2*)&sAl[r * SROW + c4 * 4] = lo;
        }
        // B chunk: 32 n x 32 k bf16 copy (uint2 per thread)
        {
            int n = t >> 3;          // 0..31
            int kc = t & 7;          // 4-elem slot
            *(uint2*)&sBh[n * SROW + kc * 4] =
                *(const uint2*)&g_W2hi[n * HH + kk + kc * 4];
            *(uint2*)&sBl[n * SROW + kc * 4] =
                *(const uint2*)&g_W2lo[n * HH + kk + kc * 4];
        }
        __syncthreads();

#pragma unroll
        for (int ks = 0; ks < 2; ks++) {
            int k0 = ks * 16;
            unsigned ah[2][4], al[2][4];
#pragma unroll
            for (int mt = 0; mt < 2; mt++) {
                int R = (wm * 32 + mt * 16 + lrA) * SROW + k0 + lcA;
                ldmx4(ah[mt], &sAh[R]);
                ldmx4(al[mt], &sAl[R]);
            }
            {
                int Bo = (wn * 16 + lrB) * SROW + k0 + lcB;
                unsigned bh4[4], bl4[4];
                ldmx4(bh4, &sBh[Bo]);
                ldmx4(bl4, &sBl[Bo]);
#pragma unroll
                for (int mt = 0; mt < 2; mt++) {
                    mma16816(acc[mt][0], ah[mt], bh4);
                    mma16816(acc[mt][0], ah[mt], bl4);
                    mma16816(acc[mt][0], al[mt], bh4);
                    mma16816(acc[mt][1], ah[mt], bh4 + 2);
                    mma16816(acc[mt][1], ah[mt], bl4 + 2);
                    mma16816(acc[mt][1], al[mt], bh4 + 2);
                }
            }
        }
    }

    // epilogue: fp16 h2
#pragma unroll
    for (int mt = 0; mt < 2; mt++) {
        int r0 = row0 + wm * 32 + mt * 16 + g;
        int r1 = r0 + 8;
#pragma unroll
        for (int nt = 0; nt < 2; nt++) {
            int col = wn * 16 + nt * 8 + tg * 2;
            if (r0 < M)
                *(__half2*)&g_h2[(size_t)r0 * CC + col] =
                    __floats2half2_rn(acc[mt][nt][0], acc[mt][nt][1]);
            if (r1 < M)
                *(__half2*)&g_h2[(size_t)r1 * CC + col] =
                    __floats2half2_rn(acc[mt][nt][2], acc[mt][nt][3]);
        }
    }
}

// ---------------- gather layer 2 + bias + log_softmax (fp16 h2, fused) ----------------
__global__ __launch_bounds__(256) void final_kernel(
    const float* __restrict__ b2, float* __restrict__ out, int n) {
    int node = (blockIdx.x << 3) + (threadIdx.x >> 5);
    int lane = threadIdx.x & 31;
    if (node >= n) return;
    float dn = g_dinv[node];
    int start = g_rowptr[node];
    int cnt = g_counts[node];
    float acc = 0.f;
    for (int j0 = 0; j0 < cnt; j0 += 32) {
        int nb = min(32, cnt - j0);
        int s = 0;
        float ds = 0.f;
        if (lane < nb) {
            s = g_csr_src[start + j0 + lane];
            ds = g_dinv[s];
        }
        for (int j = 0; j < nb; j++) {
            int sj = __shfl_sync(0xffffffffu, s, j);
            float w = __shfl_sync(0xffffffffu, ds, j) * dn;
            acc += __half2float(g_h2[(size_t)sj * CC + lane]) * w;
        }
    }
    float v = acc + b2[lane];
    float m = v;
#pragma unroll
    for (int o = 16; o > 0; o >>= 1) m = fmaxf(m, __shfl_xor_sync(0xffffffffu, m, o));
    float e = __expf(v - m);
    float ssum = e;
#pragma unroll
    for (int o = 16; o > 0; o >>= 1) ssum += __shfl_xor_sync(0xffffffffu, ssum, o);
    out[(size_t)node * CC + lane] = v - m - logf(ssum);
}

// ---------------- launcher ----------------
extern "C" void kernel_launch(void* const* d_in, const int* in_sizes, int n_in,
                              void* d_out, int out_size) {
    const float* X  = (const float*)d_in[0];
    const float* W1 = (const float*)d_in[1];
    const float* b1 = (const float*)d_in[2];
    const float* W2 = (const float*)d_in[3];
    const float* b2 = (const float*)d_in[4];
    const void*  EI = d_in[5];
    float* out = (float*)d_out;

    int N = in_sizes[0] / FF;   // 100000
    int E = in_sizes[5] / 2;    // 1600000

    int gN = (N + 255) / 256;
    int gE4 = (E / 4 + 255) / 256;
    int gW = (N + 7) / 8;

    // launch order: gemm1 is #4 so the profiler (-s 5 -c 1) captures it
    zero_detect_kernel<<<gN, 256>>>((const unsigned*)EI, N);     // 1
    prep_w_kernel<<<(FF * HH + 255) / 256, 256>>>(W1, W2);       // 2
    hist_kernel<<<gE4, 256>>>(EI, E);                            // 3
    gemm1_mma_kernel<<<(N + 127) / 128, 256>>>(X, N);            // 4
    scan1_kernel<<<gN, 256>>>(N);                                // 5
    scan2_kernel<<<1, 512>>>(gN);                                // 6
    scan3_kernel<<<gN, 256>>>(N);                                // 7
    scatter_kernel<<<gE4, 256>>>(EI, E);                         // 8
    gather1_kernel<<<gW, 256>>>(N);                              // 9
    gemm2_mma_kernel<<<(N + 127) / 128, 256>>>(b1, N);           // 10
    final_kernel<<<gW, 256>>>(b2, out, N);                       // 11
}